// round 2
// baseline (speedup 1.0000x reference)
#include <cuda_runtime.h>
#include <cuda_bf16.h>
#include <math.h>

// ---------------------------------------------------------------------------
// Problem constants
// ---------------------------------------------------------------------------
#define NB   128          // batch N
#define CC   64           // channels C = O
#define TT   64           // T
#define VV   25           // V
#define PP   (TT*VV)      // 1600 positions per (n, channel)
#define SS   3            // spatial heads
#define NTV  (NB*TT*VV)   // 204800 samples per channel for BN

// ---------------------------------------------------------------------------
// Scratch (device globals; no allocation allowed)
// ---------------------------------------------------------------------------
__device__ float g_qk  [ (size_t)NB*96*PP ];        // spatial qk conv out
__device__ float g_atts[ (size_t)NB*SS*TT*VV*VV ];  // spatial attention
__device__ float g_y   [ (size_t)NB*192*PP ];       // spatial attended
__device__ float g_conv[ (size_t)NB*CC*PP ];        // generic conv output
__device__ float g_sout[ (size_t)NB*CC*PP ];        // s_out == t_in
__device__ float g_b1  [ (size_t)NB*CC*PP ];
__device__ float g_b2  [ (size_t)NB*CC*PP ];
__device__ float g_xbar[ (size_t)NB*CC*TT ];        // mean over V
__device__ float g_qkt [ (size_t)NB*128*TT ];
__device__ float g_attt[ (size_t)NB*4*TT*TT ];      // 4 slots: f0,f1,b0,b1
__device__ float g_z   [ (size_t)NB*256*PP ];       // temporal attended
__device__ float g_stats[5*128];                    // 5 BNs x (sum[64], sumsq[64])

// ---------------------------------------------------------------------------
// Generic batched 1x1 conv = per-n GEMM:  Y[n][o][p] = sum_c W[o][c] X[n][c][p]
// grid: (P/64, ceil(COUT/64), N), block 256, BM=BN=64, BK=16, 4x4 per thread.
// If stats != nullptr, also accumulates per-channel sum/sumsq into stats
// (fused BatchNorm statistics — saves a full re-read of the output tensor).
// ---------------------------------------------------------------------------
__global__ __launch_bounds__(256) void sgemm_conv(
    const float* __restrict__ X, const float* __restrict__ W,
    const float* __restrict__ bias, float* __restrict__ Y,
    int CIN, int COUT, int P, float* __restrict__ stats)
{
    const int n  = blockIdx.z;
    const int m0 = blockIdx.y * 64;
    const int p0 = blockIdx.x * 64;
    const float* Xn = X + (size_t)n * CIN * P;
    float*       Yn = Y + (size_t)n * COUT * P;

    __shared__ float As[16][68];   // [k][m]
    __shared__ float Bs[16][68];   // [k][p]
    float acc[4][4];
    #pragma unroll
    for (int i = 0; i < 4; i++)
        #pragma unroll
        for (int j = 0; j < 4; j++) acc[i][j] = 0.f;

    const int tx = threadIdx.x & 15;   // p-group
    const int ty = threadIdx.x >> 4;   // m-group

    for (int k0 = 0; k0 < CIN; k0 += 16) {
        for (int i = threadIdx.x; i < 64 * 16; i += 256) {
            int m = i >> 4, k = i & 15;
            float w = 0.f;
            if (m0 + m < COUT) w = W[(size_t)(m0 + m) * CIN + k0 + k];
            As[k][m] = w;
        }
        for (int i = threadIdx.x; i < 16 * 64; i += 256) {
            int k = i >> 6, p = i & 63;
            Bs[k][p] = Xn[(size_t)(k0 + k) * P + p0 + p];
        }
        __syncthreads();
        #pragma unroll
        for (int k = 0; k < 16; k++) {
            float a[4], b[4];
            #pragma unroll
            for (int i = 0; i < 4; i++) a[i] = As[k][ty * 4 + i];
            #pragma unroll
            for (int j = 0; j < 4; j++) b[j] = Bs[k][tx * 4 + j];
            #pragma unroll
            for (int i = 0; i < 4; i++)
                #pragma unroll
                for (int j = 0; j < 4; j++) acc[i][j] += a[i] * b[j];
        }
        __syncthreads();
    }
    #pragma unroll
    for (int i = 0; i < 4; i++) {
        int m = m0 + ty * 4 + i;
        if (m < COUT) {
            float bv = bias ? bias[m] : 0.f;
            #pragma unroll
            for (int j = 0; j < 4; j++)
                Yn[(size_t)m * P + p0 + tx * 4 + j] = acc[i][j] + bv;
        }
    }
    if (stats) {
        // fused BN statistics (bias is always nullptr on these paths)
        #pragma unroll
        for (int i = 0; i < 4; i++) {
            float s = 0.f, s2 = 0.f;
            #pragma unroll
            for (int j = 0; j < 4; j++) {
                float v = acc[i][j];
                s += v; s2 += v * v;
            }
            // reduce across the 16 tx-lanes (consecutive within warp)
            #pragma unroll
            for (int o = 8; o > 0; o >>= 1) {
                s  += __shfl_down_sync(0xffffffffu, s,  o, 16);
                s2 += __shfl_down_sync(0xffffffffu, s2, o, 16);
            }
            if (tx == 0) {
                int m = m0 + ty * 4 + i;
                if (m < COUT) {
                    atomicAdd(&stats[m], s);
                    atomicAdd(&stats[64 + m], s2);
                }
            }
        }
    }
}

// ---------------------------------------------------------------------------
// Spatial attention: per (n,s,t) the 25x25 matrix
//  att[u,v] = att0[s,u,v] + tanh( (1/16) sum_c q[c,u] k[c,v] ) * alpha[s]
// ---------------------------------------------------------------------------
__global__ __launch_bounds__(256) void spatial_att(
    const float* __restrict__ qk, const float* __restrict__ att0,
    const float* __restrict__ alphas, float* __restrict__ atts)
{
    int b = blockIdx.x;
    int t = b % TT; int s = (b / TT) % SS; int n = b / (TT * SS);
    __shared__ float qs[16][25], ks2[16][25];
    const float* base = qk + (size_t)n * 96 * PP + t * VV;
    for (int i = threadIdx.x; i < 16 * 25; i += 256) {
        int c = i / 25, u = i % 25;
        qs [c][u] = base[(size_t)(s * 16 + c)      * PP + u];
        ks2[c][u] = base[(size_t)(48 + s * 16 + c) * PP + u];
    }
    __syncthreads();
    float alpha = alphas[s];
    float* outp = atts + ((size_t)(n * SS + s) * TT + t) * 625;
    const float* a0 = att0 + (size_t)s * 625;
    for (int i = threadIdx.x; i < 625; i += 256) {
        int u = i / 25, v = i % 25;
        float d = 0.f;
        #pragma unroll
        for (int c = 0; c < 16; c++) d += qs[c][u] * ks2[c][v];
        outp[i] = a0[i] + tanhf(d * (1.f / 16.f)) * alpha;
    }
}

// y[n, s*64+c, t, v] = sum_u x[n,c,t,u] * att[n,s,t,u,v]
__global__ __launch_bounds__(256) void spatial_apply(
    const float* __restrict__ x, const float* __restrict__ atts,
    float* __restrict__ y)
{
    int b = blockIdx.x;
    int t = b % TT; int n = b / TT;
    __shared__ float xs[64][25];
    __shared__ float as[3][25][25];
    const float* xb = x + (size_t)n * CC * PP + t * VV;
    for (int i = threadIdx.x; i < 64 * 25; i += 256) {
        int c = i / 25, u = i % 25;
        xs[c][u] = xb[(size_t)c * PP + u];
    }
    const float* ab = atts + (size_t)n * SS * TT * 625 + (size_t)t * 625;
    for (int i = threadIdx.x; i < 3 * 625; i += 256) {
        int s = i / 625, r = i % 625;
        as[s][r / 25][r % 25] = ab[(size_t)s * TT * 625 + r];
    }
    __syncthreads();
    float* yb = y + (size_t)n * 192 * PP + t * VV;
    for (int i = threadIdx.x; i < 3 * 64 * 25; i += 256) {
        int v = i % 25; int c = (i / 25) % 64; int s = i / (25 * 64);
        float acc = 0.f;
        #pragma unroll
        for (int u = 0; u < 25; u++) acc += xs[c][u] * as[s][u][v];
        yb[(size_t)(s * 64 + c) * PP + v] = acc;
    }
}

__global__ void zero_stats_kernel(float* s)
{
    int i = blockIdx.x * blockDim.x + threadIdx.x;
    if (i < 5 * 128) s[i] = 0.f;
}

// out[i] = leaky( res[i] + gamma_c*(conv[i]-mu_c)*rsqrt(var_c+eps) + beta_c )
__global__ __launch_bounds__(256) void bn_apply(
    const float* __restrict__ conv, const float* __restrict__ res,
    const float* __restrict__ gamma, const float* __restrict__ beta,
    const float* __restrict__ stats, float* __restrict__ out)
{
    size_t i = (size_t)blockIdx.x * blockDim.x + threadIdx.x;
    if (i >= (size_t)NB * CC * PP) return;
    int c = (int)((i / PP) & 63);
    float mu  = stats[c] * (1.f / (float)NTV);
    float var = stats[64 + c] * (1.f / (float)NTV) - mu * mu;
    float g = gamma[c] * rsqrtf(var + 1e-5f);
    float v = res[i] + (conv[i] - mu) * g + beta[c];
    out[i] = v > 0.f ? v : 0.1f * v;
}

// ---------------------------------------------------------------------------
// Temporal path
// ---------------------------------------------------------------------------
__global__ void mean_v_kernel(const float* __restrict__ X, float* __restrict__ xb)
{
    int i = blockIdx.x * blockDim.x + threadIdx.x;  // over N*C*T
    if (i >= NB * CC * TT) return;
    const float* p = X + (size_t)i * VV;
    float s = 0.f;
    #pragma unroll
    for (int v = 0; v < VV; v++) s += p[v];
    xb[i] = s * (1.f / (float)VV);
}

// att_f (slot 0,1) / att_b (slot 2,3), per (n,slot): 64x64 with tanh+mask
__global__ __launch_bounds__(256) void temporal_att(
    const float* __restrict__ qkt, const float* __restrict__ alphaf,
    const float* __restrict__ alphab, float* __restrict__ attt)
{
    int b = blockIdx.x;
    int slot = b & 3; int n = b >> 2;
    int dir = slot >> 1, s = slot & 1;
    int qg = (dir == 0) ? s : 2 + s;
    int kg = (dir == 0) ? 4 + s : 6 + s;
    __shared__ float qs[16][64], ks2[16][64];
    const float* base = qkt + (size_t)n * 128 * TT;
    for (int i = threadIdx.x; i < 16 * 64; i += 256) {
        int c = i >> 6, t = i & 63;
        qs [c][t] = base[(size_t)(qg * 16 + c) * TT + t];
        ks2[c][t] = base[(size_t)(kg * 16 + c) * TT + t];
    }
    __syncthreads();
    float alpha = (dir == 0) ? alphaf[s] : alphab[s];
    float* outp = attt + ((size_t)n * 4 + slot) * TT * TT;
    for (int i = threadIdx.x; i < TT * TT; i += 256) {
        int t = i >> 6, q = i & 63;
        bool keep = (dir == 0) ? (t >= q) : (q >= t);
        float d = 0.f;
        #pragma unroll
        for (int c = 0; c < 16; c++) d += qs[c][t] * ks2[c][q];
        outp[i] = keep ? tanhf(d * (1.f / 16.f)) * alpha : 0.f;
    }
}

// z[n, chbase+c, q, v] = sum_t tin[n,c,t,v] * att[t,q]
__global__ __launch_bounds__(256) void temporal_apply(
    const float* __restrict__ tin, const float* __restrict__ attt,
    float* __restrict__ z)
{
    int b = blockIdx.x;
    int slot = b & 3; int n = b >> 2;
    int dir = slot >> 1, s = slot & 1;
    int chbase = dir * 128 + s * 64;
    __shared__ float as[64][65];
    const float* ap = attt + ((size_t)n * 4 + slot) * TT * TT;
    for (int i = threadIdx.x; i < TT * TT; i += 256) as[i >> 6][i & 63] = ap[i];
    __syncthreads();
    const float* tb = tin + (size_t)n * CC * PP;
    float*       zb = z   + (size_t)n * 256 * PP;
    for (int r = threadIdx.x; r < CC * VV; r += 256) {
        int c = r / 25, v = r % 25;
        float acc[64];
        #pragma unroll
        for (int q = 0; q < 64; q++) acc[q] = 0.f;
        const float* tp = tb + (size_t)c * PP + v;
        for (int t = 0; t < 64; t++) {
            float a = tp[t * 25];
            #pragma unroll
            for (int q = 0; q < 64; q++) acc[q] += a * as[t][q];
        }
        float* zp = zb + (size_t)(chbase + c) * PP + v;
        #pragma unroll
        for (int q = 0; q < 64; q++) zp[q * 25] = acc[q];
    }
}

// ---------------------------------------------------------------------------
// TCN: 7-tap conv along T. grid (T, N), block 512, out[n,:,t,:] (64x25)
// Fused BN statistics via shared-memory reduction + global atomics.
// ---------------------------------------------------------------------------
__global__ __launch_bounds__(512) void tcn_kernel(
    const float* __restrict__ zin, const float* __restrict__ Wt,
    float* __restrict__ out, float* __restrict__ stats)
{
    int t = blockIdx.x, n = blockIdx.y;
    __shared__ float zs[16][7][25];   // c-chunk, dt, v
    __shared__ float ws[64][16][7];
    __shared__ float ssum[64], ssum2[64];
    if (threadIdx.x < 64) { ssum[threadIdx.x] = 0.f; ssum2[threadIdx.x] = 0.f; }
    float acc[4];
    #pragma unroll
    for (int i = 0; i < 4; i++) acc[i] = 0.f;
    const float* zn = zin + (size_t)n * CC * PP;
    for (int c0 = 0; c0 < 64; c0 += 16) {
        for (int i = threadIdx.x; i < 16 * 7 * 25; i += 512) {
            int c = i / 175; int rem = i % 175; int dt = rem / 25; int v = rem % 25;
            int tt = t + dt - 3;
            float val = 0.f;
            if (tt >= 0 && tt < TT) val = zn[(size_t)(c0 + c) * PP + tt * 25 + v];
            zs[c][dt][v] = val;
        }
        for (int i = threadIdx.x; i < 64 * 16 * 7; i += 512) {
            int o = i / 112; int rem = i % 112; int c = rem / 7; int dt = rem % 7;
            ws[o][c][dt] = Wt[((size_t)o * 64 + c0 + c) * 7 + dt];
        }
        __syncthreads();
        #pragma unroll
        for (int it = 0; it < 4; it++) {
            int idx = threadIdx.x + it * 512;
            if (idx < 1600) {
                int o = idx / 25, v = idx % 25;
                float a = acc[it];
                #pragma unroll
                for (int c = 0; c < 16; c++)
                    #pragma unroll
                    for (int dt = 0; dt < 7; dt++)
                        a += ws[o][c][dt] * zs[c][dt][v];
                acc[it] = a;
            }
        }
        __syncthreads();
    }
    float* op = out + (size_t)n * CC * PP + t * 25;
    #pragma unroll
    for (int it = 0; it < 4; it++) {
        int idx = threadIdx.x + it * 512;
        if (idx < 1600) {
            int o = idx / 25, v = idx % 25;
            float val = acc[it];
            op[(size_t)o * PP + v] = val;
            atomicAdd(&ssum[o], val);
            atomicAdd(&ssum2[o], val * val);
        }
    }
    __syncthreads();
    if (threadIdx.x < 64) {
        atomicAdd(&stats[threadIdx.x], ssum[threadIdx.x]);
        atomicAdd(&stats[64 + threadIdx.x], ssum2[threadIdx.x]);
    }
}

// ---------------------------------------------------------------------------
// Launcher
// ---------------------------------------------------------------------------
static float* sym(const void* symbol)
{
    void* p = nullptr;
    cudaGetSymbolAddress(&p, symbol);
    return (float*)p;
}

extern "C" void kernel_launch(void* const* d_in, const int* in_sizes, int n_in,
                              void* d_out, int out_size)
{
    const float* x       = (const float*)d_in[0];
    const float* att0s   = (const float*)d_in[1];
    const float* alphas  = (const float*)d_in[2];
    const float* W_qk_s  = (const float*)d_in[3];
    const float* b_qk_s  = (const float*)d_in[4];
    const float* W_outs  = (const float*)d_in[5];
    const float* g_outs  = (const float*)d_in[7];
    const float* be_outs = (const float*)d_in[8];
    const float* W_ffs   = (const float*)d_in[9];
    const float* g_ffs   = (const float*)d_in[11];
    const float* be_ffs  = (const float*)d_in[12];
    const float* W_qk_t  = (const float*)d_in[13];
    const float* b_qk_t  = (const float*)d_in[14];
    const float* al_f    = (const float*)d_in[15];
    const float* al_b    = (const float*)d_in[16];
    const float* W_outt  = (const float*)d_in[17];
    const float* g_outt  = (const float*)d_in[19];
    const float* be_outt = (const float*)d_in[20];
    const float* W_fft   = (const float*)d_in[21];
    const float* g_fft   = (const float*)d_in[23];
    const float* be_fft  = (const float*)d_in[24];
    const float* W_tcn   = (const float*)d_in[25];
    const float* g_tcn   = (const float*)d_in[27];
    const float* be_tcn  = (const float*)d_in[28];
    float* out = (float*)d_out;

    float* p_qk   = sym(g_qk);
    float* p_atts = sym(g_atts);
    float* p_y    = sym(g_y);
    float* p_conv = sym(g_conv);
    float* p_sout = sym(g_sout);
    float* p_b1   = sym(g_b1);
    float* p_b2   = sym(g_b2);
    float* p_xbar = sym(g_xbar);
    float* p_qkt  = sym(g_qkt);
    float* p_attt = sym(g_attt);
    float* p_z    = sym(g_z);
    float* p_st   = sym(g_stats);

    const size_t TOT = (size_t)NB * CC * PP;
    const int EW_BLOCKS = (int)((TOT + 255) / 256);

    zero_stats_kernel<<<3, 256>>>(p_st);

    // --- spatial attention ---
    sgemm_conv<<<dim3(PP / 64, 2, NB), 256>>>(x, W_qk_s, b_qk_s, p_qk, 64, 96, PP, nullptr);
    spatial_att<<<NB * SS * TT, 256>>>(p_qk, att0s, alphas, p_atts);
    spatial_apply<<<NB * TT, 256>>>(x, p_atts, p_y);

    // y = BN(conv(y, W_outs)); y = leaky(x + y)   [bias cancels in BN]
    sgemm_conv<<<dim3(PP / 64, 1, NB), 256>>>(p_y, W_outs, nullptr, p_conv, 192, 64, PP, p_st + 0);
    bn_apply<<<EW_BLOCKS, 256>>>(p_conv, x, g_outs, be_outs, p_st + 0, p_b1);

    // y = BN(conv(y, W_ffs)); s_out = leaky(x + y)
    sgemm_conv<<<dim3(PP / 64, 1, NB), 256>>>(p_b1, W_ffs, nullptr, p_conv, 64, 64, PP, p_st + 128);
    bn_apply<<<EW_BLOCKS, 256>>>(p_conv, x, g_ffs, be_ffs, p_st + 128, p_sout);

    // --- temporal attention ---
    mean_v_kernel<<<(NB * CC * TT + 255) / 256, 256>>>(p_sout, p_xbar);
    sgemm_conv<<<dim3(1, 2, NB), 256>>>(p_xbar, W_qk_t, b_qk_t, p_qkt, 64, 128, TT, nullptr);
    temporal_att<<<NB * 4, 256>>>(p_qkt, al_f, al_b, p_attt);
    temporal_apply<<<NB * 4, 256>>>(p_sout, p_attt, p_z);

    // z = BN(conv(z, W_outt)); z = leaky(t_in + z)
    sgemm_conv<<<dim3(PP / 64, 1, NB), 256>>>(p_z, W_outt, nullptr, p_conv, 256, 64, PP, p_st + 256);
    bn_apply<<<EW_BLOCKS, 256>>>(p_conv, p_sout, g_outt, be_outt, p_st + 256, p_b1);

    // z = BN(conv(z, W_fft)); z = leaky(t_in + z)
    sgemm_conv<<<dim3(PP / 64, 1, NB), 256>>>(p_b1, W_fft, nullptr, p_conv, 64, 64, PP, p_st + 384);
    bn_apply<<<EW_BLOCKS, 256>>>(p_conv, p_sout, g_fft, be_fft, p_st + 384, p_b2);

    // --- TCN ---
    tcn_kernel<<<dim3(TT, NB), 512>>>(p_b2, W_tcn, p_conv, p_st + 512);
    bn_apply<<<EW_BLOCKS, 256>>>(p_conv, p_b2, g_tcn, be_tcn, p_st + 512, out);
}

// round 5
// speedup vs baseline: 1.4904x; 1.4904x over previous
#include <cuda_runtime.h>
#include <cuda_bf16.h>
#include <math.h>

// ---------------------------------------------------------------------------
// Problem constants
// ---------------------------------------------------------------------------
#define NB   128          // batch N
#define CC   64           // channels C = O
#define TT   64           // T
#define VV   25           // V
#define PP   (TT*VV)      // 1600 positions per (n, channel)
#define SS   3            // spatial heads
#define NTV  (NB*TT*VV)   // 204800 samples per channel for BN

// ---------------------------------------------------------------------------
// Scratch (device globals; no allocation allowed)
// ---------------------------------------------------------------------------
__device__ float g_qk  [ (size_t)NB*96*PP ];        // spatial qk conv out
__device__ float g_atts[ (size_t)NB*SS*TT*VV*VV ];  // spatial attention
__device__ float g_y   [ (size_t)NB*192*PP ];       // spatial attended
__device__ float g_conv[ (size_t)NB*CC*PP ];        // generic conv output
__device__ float g_sout[ (size_t)NB*CC*PP ];        // s_out == t_in
__device__ float g_b1  [ (size_t)NB*CC*PP ];
__device__ float g_b2  [ (size_t)NB*CC*PP ];
__device__ float g_xbar[ (size_t)NB*CC*TT ];        // mean over V
__device__ float g_qkt [ (size_t)NB*128*TT ];
__device__ float g_attt[ (size_t)NB*4*TT*TT ];      // 4 slots: f0,f1,b0,b1
__device__ float g_z   [ (size_t)NB*256*PP ];       // temporal attended
__device__ float g_stats[5*128];                    // 5 BNs x (sum[64], sumsq[64])

// ---------------------------------------------------------------------------
// High-throughput GEMM for 1x1 convs (and the TCN as a K=448 GEMM).
//   Y[n][m][p] = sum_k A[m][k] * B[k][p]      (per n)
// TCN==0: A=W (COUT x CIN), B[k][p] = X[n][k][p]
// TCN==1: A=W_tcn flattened (64 x 448), k=(c*7+dt),
//         B[k][p] = X[n][c][p + (dt-3)*25] with zero fill out of range.
// Tile: BM=64, BN=128, BK=16; 256 threads; 4x8 microtile; float4 everywhere.
// grid: (ceil(1600/128)=13, ceil(COUT/64), NB)
// If stats != nullptr, fuses per-channel sum/sumsq (bias must be nullptr).
// NOTE: phantom tile columns (p0+p >= P) MUST stay zero in Bs so that their
// accumulators are zero and do not pollute the fused BN statistics. The TCN
// path therefore guards on (p0+p < P) in addition to the shifted src range.
// ---------------------------------------------------------------------------
template<int TCN>
__global__ __launch_bounds__(256) void sgemm2(
    const float* __restrict__ X, const float* __restrict__ W,
    const float* __restrict__ bias, float* __restrict__ Y,
    int CIN, int COUT, float* __restrict__ stats)
{
    const int P  = PP;
    const int n  = blockIdx.z;
    const int m0 = blockIdx.y * 64;
    const int p0 = blockIdx.x * 128;
    const float* Xn = X + (size_t)n * (TCN ? 64 : CIN) * P;
    float*       Yn = Y + (size_t)n * COUT * P;

    __shared__ __align__(16) float As[16][64];
    __shared__ __align__(16) float Bs[16][132];

    float acc[4][8];
    #pragma unroll
    for (int i = 0; i < 4; i++)
        #pragma unroll
        for (int j = 0; j < 8; j++) acc[i][j] = 0.f;

    const int tx = threadIdx.x & 15;   // column group (8 cols)
    const int ty = threadIdx.x >> 4;   // row group (4 rows)

    for (int k0 = 0; k0 < CIN; k0 += 16) {
        // ---- load A tile (64 m x 16 k), 4 elements/thread ----
        #pragma unroll
        for (int i = 0; i < 4; i++) {
            int idx = threadIdx.x + i * 256;     // 0..1023
            int m = idx >> 4, k = idx & 15;
            float w = 0.f;
            if (m0 + m < COUT) w = W[(size_t)(m0 + m) * CIN + k0 + k];
            As[k][m] = w;
        }
        // ---- load B tile (16 k x 128 p) ----
        if (!TCN) {
            #pragma unroll
            for (int i = 0; i < 2; i++) {
                int f = threadIdx.x + i * 256;   // 0..511 float4 slots
                int k = f >> 5, p = (f & 31) * 4;
                float4 v = make_float4(0.f, 0.f, 0.f, 0.f);
                if (p0 + p < P)
                    v = *(const float4*)&Xn[(size_t)(k0 + k) * P + p0 + p];
                *(float4*)&Bs[k][p] = v;
            }
        } else {
            #pragma unroll
            for (int i = 0; i < 8; i++) {
                int idx = threadIdx.x + i * 256; // 0..2047
                int k = idx >> 7, p = idx & 127;
                int kk = k0 + k;
                int c = kk / 7, dt = kk % 7;
                int src = p0 + p + (dt - 3) * 25;
                float v = 0.f;
                // (p0+p < P) keeps phantom columns zero -> clean fused stats.
                if ((p0 + p) < P && src >= 0 && src < P)
                    v = Xn[(size_t)c * P + src];
                Bs[k][p] = v;
            }
        }
        __syncthreads();
        // ---- compute ----
        #pragma unroll
        for (int k = 0; k < 16; k++) {
            float a[4], b[8];
            *(float4*)a       = *(const float4*)&As[k][ty * 4];
            *(float4*)b       = *(const float4*)&Bs[k][tx * 8];
            *(float4*)(b + 4) = *(const float4*)&Bs[k][tx * 8 + 4];
            #pragma unroll
            for (int i = 0; i < 4; i++)
                #pragma unroll
                for (int j = 0; j < 8; j++) acc[i][j] += a[i] * b[j];
        }
        __syncthreads();
    }

    // ---- epilogue ----
    #pragma unroll
    for (int i = 0; i < 4; i++) {
        int m = m0 + ty * 4 + i;
        if (m < COUT) {
            float bv = bias ? bias[m] : 0.f;
            #pragma unroll
            for (int j = 0; j < 8; j += 4) {
                int p = p0 + tx * 8 + j;
                if (p < P) {
                    float4 v = make_float4(acc[i][j] + bv, acc[i][j + 1] + bv,
                                           acc[i][j + 2] + bv, acc[i][j + 3] + bv);
                    *(float4*)&Yn[(size_t)m * P + p] = v;
                }
            }
        }
    }
    if (stats) {
        // zero-padded (out-of-range) columns contribute 0 to both moments.
        #pragma unroll
        for (int i = 0; i < 4; i++) {
            float s = 0.f, s2 = 0.f;
            #pragma unroll
            for (int j = 0; j < 8; j++) { float v = acc[i][j]; s += v; s2 += v * v; }
            #pragma unroll
            for (int o = 8; o > 0; o >>= 1) {
                s  += __shfl_down_sync(0xffffffffu, s,  o, 16);
                s2 += __shfl_down_sync(0xffffffffu, s2, o, 16);
            }
            if (tx == 0) {
                int m = m0 + ty * 4 + i;
                if (m < COUT) {
                    atomicAdd(&stats[m], s);
                    atomicAdd(&stats[64 + m], s2);
                }
            }
        }
    }
}

// ---------------------------------------------------------------------------
// Small GEMM for qk_t (P=64 columns only): original 64x64 tiling.
// ---------------------------------------------------------------------------
__global__ __launch_bounds__(256) void sgemm_small(
    const float* __restrict__ X, const float* __restrict__ W,
    const float* __restrict__ bias, float* __restrict__ Y,
    int CIN, int COUT, int P)
{
    const int n  = blockIdx.z;
    const int m0 = blockIdx.y * 64;
    const float* Xn = X + (size_t)n * CIN * P;
    float*       Yn = Y + (size_t)n * COUT * P;

    __shared__ float As[16][68];
    __shared__ float Bs[16][68];
    float acc[4][4];
    #pragma unroll
    for (int i = 0; i < 4; i++)
        #pragma unroll
        for (int j = 0; j < 4; j++) acc[i][j] = 0.f;

    const int tx = threadIdx.x & 15;
    const int ty = threadIdx.x >> 4;

    for (int k0 = 0; k0 < CIN; k0 += 16) {
        for (int i = threadIdx.x; i < 64 * 16; i += 256) {
            int m = i >> 4, k = i & 15;
            float w = 0.f;
            if (m0 + m < COUT) w = W[(size_t)(m0 + m) * CIN + k0 + k];
            As[k][m] = w;
        }
        for (int i = threadIdx.x; i < 16 * 64; i += 256) {
            int k = i >> 6, p = i & 63;
            Bs[k][p] = (p < P) ? Xn[(size_t)(k0 + k) * P + p] : 0.f;
        }
        __syncthreads();
        #pragma unroll
        for (int k = 0; k < 16; k++) {
            float a[4], b[4];
            #pragma unroll
            for (int i = 0; i < 4; i++) a[i] = As[k][ty * 4 + i];
            #pragma unroll
            for (int j = 0; j < 4; j++) b[j] = Bs[k][tx * 4 + j];
            #pragma unroll
            for (int i = 0; i < 4; i++)
                #pragma unroll
                for (int j = 0; j < 4; j++) acc[i][j] += a[i] * b[j];
        }
        __syncthreads();
    }
    #pragma unroll
    for (int i = 0; i < 4; i++) {
        int m = m0 + ty * 4 + i;
        if (m < COUT) {
            float bv = bias ? bias[m] : 0.f;
            #pragma unroll
            for (int j = 0; j < 4; j++) {
                int p = tx * 4 + j;
                if (p < P) Yn[(size_t)m * P + p] = acc[i][j] + bv;
            }
        }
    }
}

// ---------------------------------------------------------------------------
// Spatial attention: per (n,s,t) the 25x25 matrix
// ---------------------------------------------------------------------------
__global__ __launch_bounds__(256) void spatial_att(
    const float* __restrict__ qk, const float* __restrict__ att0,
    const float* __restrict__ alphas, float* __restrict__ atts)
{
    int b = blockIdx.x;
    int t = b % TT; int s = (b / TT) % SS; int n = b / (TT * SS);
    __shared__ float qs[16][25], ks2[16][25];
    const float* base = qk + (size_t)n * 96 * PP + t * VV;
    for (int i = threadIdx.x; i < 16 * 25; i += 256) {
        int c = i / 25, u = i % 25;
        qs [c][u] = base[(size_t)(s * 16 + c)      * PP + u];
        ks2[c][u] = base[(size_t)(48 + s * 16 + c) * PP + u];
    }
    __syncthreads();
    float alpha = alphas[s];
    float* outp = atts + ((size_t)(n * SS + s) * TT + t) * 625;
    const float* a0 = att0 + (size_t)s * 625;
    for (int i = threadIdx.x; i < 625; i += 256) {
        int u = i / 25, v = i % 25;
        float d = 0.f;
        #pragma unroll
        for (int c = 0; c < 16; c++) d += qs[c][u] * ks2[c][v];
        outp[i] = a0[i] + tanhf(d * (1.f / 16.f)) * alpha;
    }
}

// y[n, s*64+c, t, v] = sum_u x[n,c,t,u] * att[n,s,t,u,v]
// 240 active threads, 4c x 5v register microtile per thread.
__global__ __launch_bounds__(256) void spatial_apply(
    const float* __restrict__ x, const float* __restrict__ atts,
    float* __restrict__ y)
{
    int b = blockIdx.x;
    int t = b % TT; int n = b / TT;
    __shared__ float xs[25][68];       // [u][c]
    __shared__ float as[3][25][26];    // [s][u][v]
    const float* xb = x + (size_t)n * CC * PP + t * VV;
    for (int i = threadIdx.x; i < 64 * 25; i += 256) {
        int c = i / 25, u = i % 25;
        xs[u][c] = xb[(size_t)c * PP + u];
    }
    const float* ab = atts + (size_t)n * SS * TT * 625 + (size_t)t * 625;
    for (int i = threadIdx.x; i < 3 * 625; i += 256) {
        int s = i / 625, r = i % 625;
        as[s][r / 25][r % 25] = ab[(size_t)s * TT * 625 + r];
    }
    __syncthreads();
    if (threadIdx.x >= 240) return;
    int s  = threadIdx.x / 80;
    int r  = threadIdx.x % 80;
    int cg = r / 5;       // 16 groups of 4 channels
    int vg = r % 5;       // 5 groups of 5 v
    float acc[4][5];
    #pragma unroll
    for (int i = 0; i < 4; i++)
        #pragma unroll
        for (int j = 0; j < 5; j++) acc[i][j] = 0.f;
    #pragma unroll
    for (int u = 0; u < 25; u++) {
        float a[4], bb[5];
        #pragma unroll
        for (int i = 0; i < 4; i++) a[i] = xs[u][cg * 4 + i];
        #pragma unroll
        for (int j = 0; j < 5; j++) bb[j] = as[s][u][vg * 5 + j];
        #pragma unroll
        for (int i = 0; i < 4; i++)
            #pragma unroll
            for (int j = 0; j < 5; j++) acc[i][j] += a[i] * bb[j];
    }
    float* yb = y + (size_t)n * 192 * PP + t * VV;
    #pragma unroll
    for (int i = 0; i < 4; i++) {
        float* yp = yb + (size_t)(s * 64 + cg * 4 + i) * PP + vg * 5;
        #pragma unroll
        for (int j = 0; j < 5; j++) yp[j] = acc[i][j];
    }
}

__global__ void zero_stats_kernel(float* s)
{
    int i = blockIdx.x * blockDim.x + threadIdx.x;
    if (i < 5 * 128) s[i] = 0.f;
}

// out = leaky( res + gamma_c*(conv-mu_c)*rsqrt(var_c+eps) + beta_c ), float4
__global__ __launch_bounds__(256) void bn_apply(
    const float4* __restrict__ conv, const float4* __restrict__ res,
    const float* __restrict__ gamma, const float* __restrict__ beta,
    const float* __restrict__ stats, float4* __restrict__ out)
{
    size_t i = (size_t)blockIdx.x * blockDim.x + threadIdx.x;
    const size_t TOT4 = (size_t)NB * CC * PP / 4;
    if (i >= TOT4) return;
    int c = (int)((i / (PP / 4)) & 63);
    float mu  = stats[c] * (1.f / (float)NTV);
    float var = stats[64 + c] * (1.f / (float)NTV) - mu * mu;
    float g = gamma[c] * rsqrtf(var + 1e-5f);
    float sh = beta[c] - mu * g;
    float4 cv = conv[i], rv = res[i], o;
    float v;
    v = rv.x + cv.x * g + sh; o.x = v > 0.f ? v : 0.1f * v;
    v = rv.y + cv.y * g + sh; o.y = v > 0.f ? v : 0.1f * v;
    v = rv.z + cv.z * g + sh; o.z = v > 0.f ? v : 0.1f * v;
    v = rv.w + cv.w * g + sh; o.w = v > 0.f ? v : 0.1f * v;
    out[i] = o;
}

// ---------------------------------------------------------------------------
// Temporal path
// ---------------------------------------------------------------------------
__global__ void mean_v_kernel(const float* __restrict__ X, float* __restrict__ xb)
{
    int i = blockIdx.x * blockDim.x + threadIdx.x;  // over N*C*T
    if (i >= NB * CC * TT) return;
    const float* p = X + (size_t)i * VV;
    float s = 0.f;
    #pragma unroll
    for (int v = 0; v < VV; v++) s += p[v];
    xb[i] = s * (1.f / (float)VV);
}

__global__ __launch_bounds__(256) void temporal_att(
    const float* __restrict__ qkt, const float* __restrict__ alphaf,
    const float* __restrict__ alphab, float* __restrict__ attt)
{
    int b = blockIdx.x;
    int slot = b & 3; int n = b >> 2;
    int dir = slot >> 1, s = slot & 1;
    int qg = (dir == 0) ? s : 2 + s;
    int kg = (dir == 0) ? 4 + s : 6 + s;
    __shared__ float qs[16][64], ks2[16][64];
    const float* base = qkt + (size_t)n * 128 * TT;
    for (int i = threadIdx.x; i < 16 * 64; i += 256) {
        int c = i >> 6, t = i & 63;
        qs [c][t] = base[(size_t)(qg * 16 + c) * TT + t];
        ks2[c][t] = base[(size_t)(kg * 16 + c) * TT + t];
    }
    __syncthreads();
    float alpha = (dir == 0) ? alphaf[s] : alphab[s];
    float* outp = attt + ((size_t)n * 4 + slot) * TT * TT;
    for (int i = threadIdx.x; i < TT * TT; i += 256) {
        int t = i >> 6, q = i & 63;
        bool keep = (dir == 0) ? (t >= q) : (q >= t);
        float d = 0.f;
        #pragma unroll
        for (int c = 0; c < 16; c++) d += qs[c][t] * ks2[c][q];
        outp[i] = keep ? tanhf(d * (1.f / 16.f)) * alpha : 0.f;
    }
}

// z[n, chbase+c, q, v] = sum_t tin[n,c,t,v] * att[t,q]
__global__ __launch_bounds__(256) void temporal_apply(
    const float* __restrict__ tin, const float* __restrict__ attt,
    float* __restrict__ z)
{
    int b = blockIdx.x;
    int slot = b & 3; int n = b >> 2;
    int dir = slot >> 1, s = slot & 1;
    int chbase = dir * 128 + s * 64;
    __shared__ float as[64][65];
    const float* ap = attt + ((size_t)n * 4 + slot) * TT * TT;
    for (int i = threadIdx.x; i < TT * TT; i += 256) as[i >> 6][i & 63] = ap[i];
    __syncthreads();
    const float* tb = tin + (size_t)n * CC * PP;
    float*       zb = z   + (size_t)n * 256 * PP;
    for (int r = threadIdx.x; r < CC * VV; r += 256) {
        int c = r / 25, v = r % 25;
        float acc[64];
        #pragma unroll
        for (int q = 0; q < 64; q++) acc[q] = 0.f;
        const float* tp = tb + (size_t)c * PP + v;
        for (int t = 0; t < 64; t++) {
            float a = tp[t * 25];
            #pragma unroll
            for (int q = 0; q < 64; q++) acc[q] += a * as[t][q];
        }
        float* zp = zb + (size_t)(chbase + c) * PP + v;
        #pragma unroll
        for (int q = 0; q < 64; q++) zp[q * 25] = acc[q];
    }
}

// ---------------------------------------------------------------------------
// Launcher
// ---------------------------------------------------------------------------
static float* sym(const void* symbol)
{
    void* p = nullptr;
    cudaGetSymbolAddress(&p, symbol);
    return (float*)p;
}

extern "C" void kernel_launch(void* const* d_in, const int* in_sizes, int n_in,
                              void* d_out, int out_size)
{
    const float* x       = (const float*)d_in[0];
    const float* att0s   = (const float*)d_in[1];
    const float* alphas  = (const float*)d_in[2];
    const float* W_qk_s  = (const float*)d_in[3];
    const float* b_qk_s  = (const float*)d_in[4];
    const float* W_outs  = (const float*)d_in[5];
    const float* g_outs  = (const float*)d_in[7];
    const float* be_outs = (const float*)d_in[8];
    const float* W_ffs   = (const float*)d_in[9];
    const float* g_ffs   = (const float*)d_in[11];
    const float* be_ffs  = (const float*)d_in[12];
    const float* W_qk_t  = (const float*)d_in[13];
    const float* b_qk_t  = (const float*)d_in[14];
    const float* al_f    = (const float*)d_in[15];
    const float* al_b    = (const float*)d_in[16];
    const float* W_outt  = (const float*)d_in[17];
    const float* g_outt  = (const float*)d_in[19];
    const float* be_outt = (const float*)d_in[20];
    const float* W_fft   = (const float*)d_in[21];
    const float* g_fft   = (const float*)d_in[23];
    const float* be_fft  = (const float*)d_in[24];
    const float* W_tcn   = (const float*)d_in[25];
    const float* g_tcn   = (const float*)d_in[27];
    const float* be_tcn  = (const float*)d_in[28];
    float* out = (float*)d_out;

    float* p_qk   = sym(g_qk);
    float* p_atts = sym(g_atts);
    float* p_y    = sym(g_y);
    float* p_conv = sym(g_conv);
    float* p_sout = sym(g_sout);
    float* p_b1   = sym(g_b1);
    float* p_b2   = sym(g_b2);
    float* p_xbar = sym(g_xbar);
    float* p_qkt  = sym(g_qkt);
    float* p_attt = sym(g_attt);
    float* p_z    = sym(g_z);
    float* p_st   = sym(g_stats);

    const size_t TOT = (size_t)NB * CC * PP;
    const int EW_BLOCKS4 = (int)((TOT / 4 + 255) / 256);
    const dim3 G13(13, 1, NB);

    zero_stats_kernel<<<3, 256>>>(p_st);

    // --- spatial attention ---
    sgemm2<0><<<dim3(13, 2, NB), 256>>>(x, W_qk_s, b_qk_s, p_qk, 64, 96, nullptr);
    spatial_att<<<NB * SS * TT, 256>>>(p_qk, att0s, alphas, p_atts);
    spatial_apply<<<NB * TT, 256>>>(x, p_atts, p_y);

    // y = BN(conv(y, W_outs)); y = leaky(x + y)   [bias cancels in BN]
    sgemm2<0><<<G13, 256>>>(p_y, W_outs, nullptr, p_conv, 192, 64, p_st + 0);
    bn_apply<<<EW_BLOCKS4, 256>>>((const float4*)p_conv, (const float4*)x,
                                  g_outs, be_outs, p_st + 0, (float4*)p_b1);

    // y = BN(conv(y, W_ffs)); s_out = leaky(x + y)
    sgemm2<0><<<G13, 256>>>(p_b1, W_ffs, nullptr, p_conv, 64, 64, p_st + 128);
    bn_apply<<<EW_BLOCKS4, 256>>>((const float4*)p_conv, (const float4*)x,
                                  g_ffs, be_ffs, p_st + 128, (float4*)p_sout);

    // --- temporal attention ---
    mean_v_kernel<<<(NB * CC * TT + 255) / 256, 256>>>(p_sout, p_xbar);
    sgemm_small<<<dim3(1, 2, NB), 256>>>(p_xbar, W_qk_t, b_qk_t, p_qkt, 64, 128, TT);
    temporal_att<<<NB * 4, 256>>>(p_qkt, al_f, al_b, p_attt);
    temporal_apply<<<NB * 4, 256>>>(p_sout, p_attt, p_z);

    // z = BN(conv(z, W_outt)); z = leaky(t_in + z)
    sgemm2<0><<<G13, 256>>>(p_z, W_outt, nullptr, p_conv, 256, 64, p_st + 256);
    bn_apply<<<EW_BLOCKS4, 256>>>((const float4*)p_conv, (const float4*)p_sout,
                                  g_outt, be_outt, p_st + 256, (float4*)p_b1);

    // z = BN(conv(z, W_fft)); z = leaky(t_in + z)
    sgemm2<0><<<G13, 256>>>(p_b1, W_fft, nullptr, p_conv, 64, 64, p_st + 384);
    bn_apply<<<EW_BLOCKS4, 256>>>((const float4*)p_conv, (const float4*)p_sout,
                                  g_fft, be_fft, p_st + 384, (float4*)p_b2);

    // --- TCN as K=448 GEMM (k = c*7+dt, shifted B rows) ---
    sgemm2<1><<<G13, 256>>>(p_b2, W_tcn, nullptr, p_conv, 448, 64, p_st + 512);
    bn_apply<<<EW_BLOCKS4, 256>>>((const float4*)p_conv, (const float4*)p_b2,
                                  g_tcn, be_tcn, p_st + 512, (float4*)out);
}

// round 6
// speedup vs baseline: 1.5546x; 1.0431x over previous
#include <cuda_runtime.h>
#include <cuda_bf16.h>
#include <math.h>

// ---------------------------------------------------------------------------
// Problem constants
// ---------------------------------------------------------------------------
#define NB   128          // batch N
#define CC   64           // channels C = O
#define TT   64           // T
#define VV   25           // V
#define PP   (TT*VV)      // 1600 positions per (n, channel)
#define SS   3            // spatial heads
#define NTV  (NB*TT*VV)   // 204800 samples per channel for BN

// ---------------------------------------------------------------------------
// Scratch (device globals; no allocation allowed)
// ---------------------------------------------------------------------------
__device__ float g_qk  [ (size_t)NB*96*PP ];        // spatial qk conv out
__device__ float g_y   [ (size_t)NB*192*PP ];       // spatial attended
__device__ float g_conv[ (size_t)NB*CC*PP ];        // generic conv output
__device__ float g_sout[ (size_t)NB*CC*PP ];        // s_out == t_in
__device__ float g_b1  [ (size_t)NB*CC*PP ];
__device__ float g_b2  [ (size_t)NB*CC*PP ];
__device__ float g_xbar[ (size_t)NB*CC*TT ];        // mean over V
__device__ float g_qkt [ (size_t)NB*128*TT ];
__device__ float g_attt[ (size_t)NB*4*TT*TT ];      // 4 slots: f0,f1,b0,b1
__device__ float g_z   [ (size_t)NB*256*PP ];       // temporal attended
__device__ float g_stats[5*128];                    // 5 BNs x (sum[64], sumsq[64])

// ---------------------------------------------------------------------------
// Software-pipelined GEMM for 1x1 convs (and the TCN as a K=448 GEMM).
//   Y[n][m][p] = sum_k A[m][k] * B[k][p]      (per n)
// TCN==0: A=W (COUT x CIN), B[k][p] = X[n][k][p]
// TCN==1: A=W_tcn flattened (64 x 448), k=(c*7+dt),
//         B[k][p] = X[n][c][p + (dt-3)*25] with zero fill out of range.
// Tile: BM=64, BN=128, BK=16; 256 threads; 4x8 microtile.
// Double-buffered smem with register prefetch staging: global loads for
// tile i+1 are issued before the FMA block of tile i; one barrier/iter.
// grid: (13, ceil(COUT/64), NB)
// If stats != nullptr, fuses per-channel sum/sumsq (bias must be nullptr).
// Phantom columns (p0+p >= P) stay zero so fused stats remain clean.
// ---------------------------------------------------------------------------
template<int TCN>
__global__ __launch_bounds__(256) void sgemm2(
    const float* __restrict__ X, const float* __restrict__ W,
    const float* __restrict__ bias, float* __restrict__ Y,
    int CIN, int COUT, float* __restrict__ stats)
{
    const int P  = PP;
    const int n  = blockIdx.z;
    const int m0 = blockIdx.y * 64;
    const int p0 = blockIdx.x * 128;
    const float* Xn = X + (size_t)n * (TCN ? 64 : CIN) * P;
    float*       Yn = Y + (size_t)n * COUT * P;

    __shared__ __align__(16) float As[2][16][64];
    __shared__ __align__(16) float Bs[2][16][132];

    float acc[4][8];
    #pragma unroll
    for (int i = 0; i < 4; i++)
        #pragma unroll
        for (int j = 0; j < 8; j++) acc[i][j] = 0.f;

    const int tx = threadIdx.x & 15;   // column group (8 cols)
    const int ty = threadIdx.x >> 4;   // row group (4 rows)

    const int nk = CIN / 16;

    // prefetch register staging
    float pa[4];
    float pb[8];

    // ---- helpers (inlined manually) ----
    // A element (m,k) of k-tile k0 for lane-mapped index idx = tid + i*256
    // A: idx>>4 = m, idx&15 = k
    // B (non-TCN): float4 slots f = tid + i*256; k=f>>5, p=(f&31)*4
    // B (TCN): idx = tid + i*256 (0..2047): k=idx>>7, p=idx&127

    // ---- initial load of tile 0 directly to smem buffer 0 ----
    {
        #pragma unroll
        for (int i = 0; i < 4; i++) {
            int idx = threadIdx.x + i * 256;
            int m = idx >> 4, k = idx & 15;
            float w = 0.f;
            if (m0 + m < COUT) w = W[(size_t)(m0 + m) * CIN + k];
            As[0][k][m] = w;
        }
        if (!TCN) {
            #pragma unroll
            for (int i = 0; i < 2; i++) {
                int f = threadIdx.x + i * 256;
                int k = f >> 5, p = (f & 31) * 4;
                float4 v = make_float4(0.f, 0.f, 0.f, 0.f);
                if (p0 + p < P)
                    v = *(const float4*)&Xn[(size_t)k * P + p0 + p];
                *(float4*)&Bs[0][k][p] = v;
            }
        } else {
            #pragma unroll
            for (int i = 0; i < 8; i++) {
                int idx = threadIdx.x + i * 256;
                int k = idx >> 7, p = idx & 127;
                int c = k / 7, dt = k % 7;
                int src = p0 + p + (dt - 3) * 25;
                float v = 0.f;
                if ((p0 + p) < P && src >= 0 && src < P)
                    v = Xn[(size_t)c * P + src];
                Bs[0][k][p] = v;
            }
        }
    }
    __syncthreads();

    for (int it = 0; it < nk; it++) {
        const int cur = it & 1;
        const bool more = (it + 1 < nk);
        const int k0n = (it + 1) * 16;

        // ---- issue next tile's global loads into registers ----
        if (more) {
            #pragma unroll
            for (int i = 0; i < 4; i++) {
                int idx = threadIdx.x + i * 256;
                int m = idx >> 4, k = idx & 15;
                float w = 0.f;
                if (m0 + m < COUT) w = W[(size_t)(m0 + m) * CIN + k0n + k];
                pa[i] = w;
            }
            if (!TCN) {
                #pragma unroll
                for (int i = 0; i < 2; i++) {
                    int f = threadIdx.x + i * 256;
                    int k = f >> 5, p = (f & 31) * 4;
                    float4 v = make_float4(0.f, 0.f, 0.f, 0.f);
                    if (p0 + p < P)
                        v = *(const float4*)&Xn[(size_t)(k0n + k) * P + p0 + p];
                    pb[i * 4 + 0] = v.x; pb[i * 4 + 1] = v.y;
                    pb[i * 4 + 2] = v.z; pb[i * 4 + 3] = v.w;
                }
            } else {
                #pragma unroll
                for (int i = 0; i < 8; i++) {
                    int idx = threadIdx.x + i * 256;
                    int k = idx >> 7, p = idx & 127;
                    int kk = k0n + k;
                    int c = kk / 7, dt = kk % 7;
                    int src = p0 + p + (dt - 3) * 25;
                    float v = 0.f;
                    if ((p0 + p) < P && src >= 0 && src < P)
                        v = Xn[(size_t)c * P + src];
                    pb[i] = v;
                }
            }
        }

        // ---- compute current tile ----
        #pragma unroll
        for (int k = 0; k < 16; k++) {
            float a[4], b[8];
            *(float4*)a       = *(const float4*)&As[cur][k][ty * 4];
            *(float4*)b       = *(const float4*)&Bs[cur][k][tx * 8];
            *(float4*)(b + 4) = *(const float4*)&Bs[cur][k][tx * 8 + 4];
            #pragma unroll
            for (int i = 0; i < 4; i++)
                #pragma unroll
                for (int j = 0; j < 8; j++) acc[i][j] += a[i] * b[j];
        }

        // ---- store prefetched tile to the other buffer ----
        if (more) {
            const int nxt = 1 - cur;
            #pragma unroll
            for (int i = 0; i < 4; i++) {
                int idx = threadIdx.x + i * 256;
                int m = idx >> 4, k = idx & 15;
                As[nxt][k][m] = pa[i];
            }
            if (!TCN) {
                #pragma unroll
                for (int i = 0; i < 2; i++) {
                    int f = threadIdx.x + i * 256;
                    int k = f >> 5, p = (f & 31) * 4;
                    float4 v = make_float4(pb[i * 4 + 0], pb[i * 4 + 1],
                                           pb[i * 4 + 2], pb[i * 4 + 3]);
                    *(float4*)&Bs[nxt][k][p] = v;
                }
            } else {
                #pragma unroll
                for (int i = 0; i < 8; i++) {
                    int idx = threadIdx.x + i * 256;
                    int k = idx >> 7, p = idx & 127;
                    Bs[nxt][k][p] = pb[i];
                }
            }
        }
        __syncthreads();
    }

    // ---- epilogue ----
    #pragma unroll
    for (int i = 0; i < 4; i++) {
        int m = m0 + ty * 4 + i;
        if (m < COUT) {
            float bv = bias ? bias[m] : 0.f;
            #pragma unroll
            for (int j = 0; j < 8; j += 4) {
                int p = p0 + tx * 8 + j;
                if (p < P) {
                    float4 v = make_float4(acc[i][j] + bv, acc[i][j + 1] + bv,
                                           acc[i][j + 2] + bv, acc[i][j + 3] + bv);
                    *(float4*)&Yn[(size_t)m * P + p] = v;
                }
            }
        }
    }
    if (stats) {
        #pragma unroll
        for (int i = 0; i < 4; i++) {
            float s = 0.f, s2 = 0.f;
            #pragma unroll
            for (int j = 0; j < 8; j++) { float v = acc[i][j]; s += v; s2 += v * v; }
            #pragma unroll
            for (int o = 8; o > 0; o >>= 1) {
                s  += __shfl_down_sync(0xffffffffu, s,  o, 16);
                s2 += __shfl_down_sync(0xffffffffu, s2, o, 16);
            }
            if (tx == 0) {
                int m = m0 + ty * 4 + i;
                if (m < COUT) {
                    atomicAdd(&stats[m], s);
                    atomicAdd(&stats[64 + m], s2);
                }
            }
        }
    }
}

// ---------------------------------------------------------------------------
// Small GEMM for qk_t (P=64 columns only).
// ---------------------------------------------------------------------------
__global__ __launch_bounds__(256) void sgemm_small(
    const float* __restrict__ X, const float* __restrict__ W,
    const float* __restrict__ bias, float* __restrict__ Y,
    int CIN, int COUT, int P)
{
    const int n  = blockIdx.z;
    const int m0 = blockIdx.y * 64;
    const float* Xn = X + (size_t)n * CIN * P;
    float*       Yn = Y + (size_t)n * COUT * P;

    __shared__ float As[16][68];
    __shared__ float Bs[16][68];
    float acc[4][4];
    #pragma unroll
    for (int i = 0; i < 4; i++)
        #pragma unroll
        for (int j = 0; j < 4; j++) acc[i][j] = 0.f;

    const int tx = threadIdx.x & 15;
    const int ty = threadIdx.x >> 4;

    for (int k0 = 0; k0 < CIN; k0 += 16) {
        for (int i = threadIdx.x; i < 64 * 16; i += 256) {
            int m = i >> 4, k = i & 15;
            float w = 0.f;
            if (m0 + m < COUT) w = W[(size_t)(m0 + m) * CIN + k0 + k];
            As[k][m] = w;
        }
        for (int i = threadIdx.x; i < 16 * 64; i += 256) {
            int k = i >> 6, p = i & 63;
            Bs[k][p] = (p < P) ? Xn[(size_t)(k0 + k) * P + p] : 0.f;
        }
        __syncthreads();
        #pragma unroll
        for (int k = 0; k < 16; k++) {
            float a[4], b[4];
            #pragma unroll
            for (int i = 0; i < 4; i++) a[i] = As[k][ty * 4 + i];
            #pragma unroll
            for (int j = 0; j < 4; j++) b[j] = Bs[k][tx * 4 + j];
            #pragma unroll
            for (int i = 0; i < 4; i++)
                #pragma unroll
                for (int j = 0; j < 4; j++) acc[i][j] += a[i] * b[j];
        }
        __syncthreads();
    }
    #pragma unroll
    for (int i = 0; i < 4; i++) {
        int m = m0 + ty * 4 + i;
        if (m < COUT) {
            float bv = bias ? bias[m] : 0.f;
            #pragma unroll
            for (int j = 0; j < 4; j++) {
                int p = tx * 4 + j;
                if (p < P) Yn[(size_t)m * P + p] = acc[i][j] + bv;
            }
        }
    }
}

// ---------------------------------------------------------------------------
// Fused spatial attention + apply: one block per (n,t).
//  att[s][u][v] = att0[s,u,v] + tanh( (1/16) sum_c q[c,u] k[c,v] ) * alpha[s]
//  y[n, s*64+c, t, v] = sum_u x[n,c,t,u] * att[s][u][v]
// ---------------------------------------------------------------------------
__global__ __launch_bounds__(256) void spatial_fused(
    const float* __restrict__ x, const float* __restrict__ qk,
    const float* __restrict__ att0, const float* __restrict__ alphas,
    float* __restrict__ y)
{
    int b = blockIdx.x;
    int t = b % TT; int n = b / TT;
    __shared__ float qs[3][16][25];
    __shared__ float ks[3][16][25];
    __shared__ float xs[25][68];       // [u][c]
    __shared__ float as[3][25][26];    // [s][u][v]

    const float* base = qk + (size_t)n * 96 * PP + t * VV;
    for (int i = threadIdx.x; i < 48 * 25; i += 256) {
        int c = i / 25, u = i % 25;       // c = s*16+cc, 0..47
        qs[c >> 4][c & 15][u] = base[(size_t)c * PP + u];
        ks[c >> 4][c & 15][u] = base[(size_t)(48 + c) * PP + u];
    }
    const float* xb = x + (size_t)n * CC * PP + t * VV;
    for (int i = threadIdx.x; i < 64 * 25; i += 256) {
        int c = i / 25, u = i % 25;
        xs[u][c] = xb[(size_t)c * PP + u];
    }
    __syncthreads();

    // attention: 3*625 = 1875 entries
    for (int i = threadIdx.x; i < 3 * 625; i += 256) {
        int s = i / 625, r = i % 625;
        int u = r / 25, v = r % 25;
        float d = 0.f;
        #pragma unroll
        for (int c = 0; c < 16; c++) d += qs[s][c][u] * ks[s][c][v];
        as[s][u][v] = att0[(size_t)s * 625 + r] + tanhf(d * (1.f / 16.f)) * alphas[s];
    }
    __syncthreads();

    // apply: 240 active threads, 4c x 5v microtile
    if (threadIdx.x >= 240) return;
    int s  = threadIdx.x / 80;
    int r  = threadIdx.x % 80;
    int cg = r / 5;
    int vg = r % 5;
    float acc[4][5];
    #pragma unroll
    for (int i = 0; i < 4; i++)
        #pragma unroll
        for (int j = 0; j < 5; j++) acc[i][j] = 0.f;
    #pragma unroll
    for (int u = 0; u < 25; u++) {
        float a[4], bb[5];
        #pragma unroll
        for (int i = 0; i < 4; i++) a[i] = xs[u][cg * 4 + i];
        #pragma unroll
        for (int j = 0; j < 5; j++) bb[j] = as[s][u][vg * 5 + j];
        #pragma unroll
        for (int i = 0; i < 4; i++)
            #pragma unroll
            for (int j = 0; j < 5; j++) acc[i][j] += a[i] * bb[j];
    }
    float* yb = y + (size_t)n * 192 * PP + t * VV;
    #pragma unroll
    for (int i = 0; i < 4; i++) {
        float* yp = yb + (size_t)(s * 64 + cg * 4 + i) * PP + vg * 5;
        #pragma unroll
        for (int j = 0; j < 5; j++) yp[j] = acc[i][j];
    }
}

__global__ void zero_stats_kernel(float* s)
{
    int i = blockIdx.x * blockDim.x + threadIdx.x;
    if (i < 5 * 128) s[i] = 0.f;
}

// out = leaky( res + gamma_c*(conv-mu_c)*rsqrt(var_c+eps) + beta_c ), float4
__global__ __launch_bounds__(256) void bn_apply(
    const float4* __restrict__ conv, const float4* __restrict__ res,
    const float* __restrict__ gamma, const float* __restrict__ beta,
    const float* __restrict__ stats, float4* __restrict__ out)
{
    size_t i = (size_t)blockIdx.x * blockDim.x + threadIdx.x;
    const size_t TOT4 = (size_t)NB * CC * PP / 4;
    if (i >= TOT4) return;
    int c = (int)((i / (PP / 4)) & 63);
    float mu  = stats[c] * (1.f / (float)NTV);
    float var = stats[64 + c] * (1.f / (float)NTV) - mu * mu;
    float g = gamma[c] * rsqrtf(var + 1e-5f);
    float sh = beta[c] - mu * g;
    float4 cv = conv[i], rv = res[i], o;
    float v;
    v = rv.x + cv.x * g + sh; o.x = v > 0.f ? v : 0.1f * v;
    v = rv.y + cv.y * g + sh; o.y = v > 0.f ? v : 0.1f * v;
    v = rv.z + cv.z * g + sh; o.z = v > 0.f ? v : 0.1f * v;
    v = rv.w + cv.w * g + sh; o.w = v > 0.f ? v : 0.1f * v;
    out[i] = o;
}

// ---------------------------------------------------------------------------
// Temporal path
// ---------------------------------------------------------------------------
__global__ void mean_v_kernel(const float* __restrict__ X, float* __restrict__ xb)
{
    int i = blockIdx.x * blockDim.x + threadIdx.x;  // over N*C*T
    if (i >= NB * CC * TT) return;
    const float* p = X + (size_t)i * VV;
    float s = 0.f;
    #pragma unroll
    for (int v = 0; v < VV; v++) s += p[v];
    xb[i] = s * (1.f / (float)VV);
}

__global__ __launch_bounds__(256) void temporal_att(
    const float* __restrict__ qkt, const float* __restrict__ alphaf,
    const float* __restrict__ alphab, float* __restrict__ attt)
{
    int b = blockIdx.x;
    int slot = b & 3; int n = b >> 2;
    int dir = slot >> 1, s = slot & 1;
    int qg = (dir == 0) ? s : 2 + s;
    int kg = (dir == 0) ? 4 + s : 6 + s;
    __shared__ float qs[16][64], ks2[16][64];
    const float* base = qkt + (size_t)n * 128 * TT;
    for (int i = threadIdx.x; i < 16 * 64; i += 256) {
        int c = i >> 6, t = i & 63;
        qs [c][t] = base[(size_t)(qg * 16 + c) * TT + t];
        ks2[c][t] = base[(size_t)(kg * 16 + c) * TT + t];
    }
    __syncthreads();
    float alpha = (dir == 0) ? alphaf[s] : alphab[s];
    float* outp = attt + ((size_t)n * 4 + slot) * TT * TT;
    for (int i = threadIdx.x; i < TT * TT; i += 256) {
        int t = i >> 6, q = i & 63;
        bool keep = (dir == 0) ? (t >= q) : (q >= t);
        float d = 0.f;
        #pragma unroll
        for (int c = 0; c < 16; c++) d += qs[c][t] * ks2[c][q];
        outp[i] = keep ? tanhf(d * (1.f / 16.f)) * alpha : 0.f;
    }
}

// z[n, chbase+c, q, v] = sum_t tin[n,c,t,v] * att[t,q]
__global__ __launch_bounds__(256) void temporal_apply(
    const float* __restrict__ tin, const float* __restrict__ attt,
    float* __restrict__ z)
{
    int b = blockIdx.x;
    int slot = b & 3; int n = b >> 2;
    int dir = slot >> 1, s = slot & 1;
    int chbase = dir * 128 + s * 64;
    __shared__ float as[64][65];
    const float* ap = attt + ((size_t)n * 4 + slot) * TT * TT;
    for (int i = threadIdx.x; i < TT * TT; i += 256) as[i >> 6][i & 63] = ap[i];
    __syncthreads();
    const float* tb = tin + (size_t)n * CC * PP;
    float*       zb = z   + (size_t)n * 256 * PP;
    for (int r = threadIdx.x; r < CC * VV; r += 256) {
        int c = r / 25, v = r % 25;
        float acc[64];
        #pragma unroll
        for (int q = 0; q < 64; q++) acc[q] = 0.f;
        const float* tp = tb + (size_t)c * PP + v;
        for (int t = 0; t < 64; t++) {
            float a = tp[t * 25];
            #pragma unroll
            for (int q = 0; q < 64; q++) acc[q] += a * as[t][q];
        }
        float* zp = zb + (size_t)(chbase + c) * PP + v;
        #pragma unroll
        for (int q = 0; q < 64; q++) zp[q * 25] = acc[q];
    }
}

// ---------------------------------------------------------------------------
// Launcher
// ---------------------------------------------------------------------------
static float* sym(const void* symbol)
{
    void* p = nullptr;
    cudaGetSymbolAddress(&p, symbol);
    return (float*)p;
}

extern "C" void kernel_launch(void* const* d_in, const int* in_sizes, int n_in,
                              void* d_out, int out_size)
{
    const float* x       = (const float*)d_in[0];
    const float* att0s   = (const float*)d_in[1];
    const float* alphas  = (const float*)d_in[2];
    const float* W_qk_s  = (const float*)d_in[3];
    const float* b_qk_s  = (const float*)d_in[4];
    const float* W_outs  = (const float*)d_in[5];
    const float* g_outs  = (const float*)d_in[7];
    const float* be_outs = (const float*)d_in[8];
    const float* W_ffs   = (const float*)d_in[9];
    const float* g_ffs   = (const float*)d_in[11];
    const float* be_ffs  = (const float*)d_in[12];
    const float* W_qk_t  = (const float*)d_in[13];
    const float* b_qk_t  = (const float*)d_in[14];
    const float* al_f    = (const float*)d_in[15];
    const float* al_b    = (const float*)d_in[16];
    const float* W_outt  = (const float*)d_in[17];
    const float* g_outt  = (const float*)d_in[19];
    const float* be_outt = (const float*)d_in[20];
    const float* W_fft   = (const float*)d_in[21];
    const float* g_fft   = (const float*)d_in[23];
    const float* be_fft  = (const float*)d_in[24];
    const float* W_tcn   = (const float*)d_in[25];
    const float* g_tcn   = (const float*)d_in[27];
    const float* be_tcn  = (const float*)d_in[28];
    float* out = (float*)d_out;

    float* p_qk   = sym(g_qk);
    float* p_y    = sym(g_y);
    float* p_conv = sym(g_conv);
    float* p_sout = sym(g_sout);
    float* p_b1   = sym(g_b1);
    float* p_b2   = sym(g_b2);
    float* p_xbar = sym(g_xbar);
    float* p_qkt  = sym(g_qkt);
    float* p_attt = sym(g_attt);
    float* p_z    = sym(g_z);
    float* p_st   = sym(g_stats);

    const size_t TOT = (size_t)NB * CC * PP;
    const int EW_BLOCKS4 = (int)((TOT / 4 + 255) / 256);
    const dim3 G13(13, 1, NB);

    zero_stats_kernel<<<3, 256>>>(p_st);

    // --- spatial attention (fused att + apply) ---
    sgemm2<0><<<dim3(13, 2, NB), 256>>>(x, W_qk_s, b_qk_s, p_qk, 64, 96, nullptr);
    spatial_fused<<<NB * TT, 256>>>(x, p_qk, att0s, alphas, p_y);

    // y = BN(conv(y, W_outs)); y = leaky(x + y)   [bias cancels in BN]
    sgemm2<0><<<G13, 256>>>(p_y, W_outs, nullptr, p_conv, 192, 64, p_st + 0);
    bn_apply<<<EW_BLOCKS4, 256>>>((const float4*)p_conv, (const float4*)x,
                                  g_outs, be_outs, p_st + 0, (float4*)p_b1);

    // y = BN(conv(y, W_ffs)); s_out = leaky(x + y)
    sgemm2<0><<<G13, 256>>>(p_b1, W_ffs, nullptr, p_conv, 64, 64, p_st + 128);
    bn_apply<<<EW_BLOCKS4, 256>>>((const float4*)p_conv, (const float4*)x,
                                  g_ffs, be_ffs, p_st + 128, (float4*)p_sout);

    // --- temporal attention ---
    mean_v_kernel<<<(NB * CC * TT + 255) / 256, 256>>>(p_sout, p_xbar);
    sgemm_small<<<dim3(1, 2, NB), 256>>>(p_xbar, W_qk_t, b_qk_t, p_qkt, 64, 128, TT);
    temporal_att<<<NB * 4, 256>>>(p_qkt, al_f, al_b, p_attt);
    temporal_apply<<<NB * 4, 256>>>(p_sout, p_attt, p_z);

    // z = BN(conv(z, W_outt)); z = leaky(t_in + z)
    sgemm2<0><<<G13, 256>>>(p_z, W_outt, nullptr, p_conv, 256, 64, p_st + 256);
    bn_apply<<<EW_BLOCKS4, 256>>>((const float4*)p_conv, (const float4*)p_sout,
                                  g_outt, be_outt, p_st + 256, (float4*)p_b1);

    // z = BN(conv(z, W_fft)); z = leaky(t_in + z)
    sgemm2<0><<<G13, 256>>>(p_b1, W_fft, nullptr, p_conv, 64, 64, p_st + 384);
    bn_apply<<<EW_BLOCKS4, 256>>>((const float4*)p_conv, (const float4*)p_sout,
                                  g_fft, be_fft, p_st + 384, (float4*)p_b2);

    // --- TCN as K=448 GEMM (k = c*7+dt, shifted B rows) ---
    sgemm2<1><<<G13, 256>>>(p_b2, W_tcn, nullptr, p_conv, 448, 64, p_st + 512);
    bn_apply<<<EW_BLOCKS4, 256>>>((const float4*)p_conv, (const float4*)p_b2,
                                  g_tcn, be_tcn, p_st + 512, (float4*)out);
}

// round 7
// speedup vs baseline: 1.6312x; 1.0492x over previous
#include <cuda_runtime.h>
#include <cuda_bf16.h>
#include <math.h>

// ---------------------------------------------------------------------------
// Problem constants
// ---------------------------------------------------------------------------
#define NB   128          // batch N
#define CC   64           // channels C = O
#define TT   64           // T
#define VV   25           // V
#define PP   (TT*VV)      // 1600 positions per (n, channel)
#define SS   3            // spatial heads
#define NTV  (NB*TT*VV)   // 204800 samples per channel for BN

// ---------------------------------------------------------------------------
// Scratch (device globals; no allocation allowed)
// ---------------------------------------------------------------------------
__device__ float g_qk  [ (size_t)NB*96*PP ];        // spatial qk conv out
__device__ float g_y   [ (size_t)NB*192*PP ];       // spatial attended
__device__ float g_conv[ (size_t)NB*CC*PP ];        // generic conv output
__device__ float g_sout[ (size_t)NB*CC*PP ];        // s_out == t_in
__device__ float g_b1  [ (size_t)NB*CC*PP ];
__device__ float g_b2  [ (size_t)NB*CC*PP ];
__device__ float g_xbar[ (size_t)NB*CC*TT ];        // mean over V
__device__ float g_qkt [ (size_t)NB*128*TT ];
__device__ float g_attt[ (size_t)NB*4*TT*TT ];      // 4 slots: f0,f1,b0,b1
__device__ float g_z   [ (size_t)NB*256*PP ];       // temporal attended
__device__ float g_stats[5*128];                    // 5 BNs x (sum[64], sumsq[64])

// ---------------------------------------------------------------------------
// Balanced-ratio GEMM for 1x1 convs (and the TCN as a K=448 GEMM).
//   Y[n][m][p] = sum_k A[m][k] * B[k][p]      (per n)
// TCN==0: A=W (COUT x CIN), B[k][p] = X[n][k][p]
// TCN==1: A=W_tcn flattened (64 x 448), k=(c*7+dt),
//         B[k][p] = X[n][c][p + (dt-3)*25] with zero fill out of range.
// Tile: BM=64, BN=256, BK=16; 256 threads; 8x8 microtile.
//   -> per thread per k: 64 FMA / 64 B shared loads = 1.0 FMA/byte, matching
//      the SM's 128 FMA/cyc vs 128 B/cyc crossbar balance. A-reads are
//      warp-uniform (whole warp shares ty) -> broadcast, conflict-free.
// Double-buffered smem + register prefetch staging; one barrier per k-tile.
// grid: (ceil(1600/256)=7, ceil(COUT/64), NB)
// If stats != nullptr, fuses per-channel sum/sumsq (bias must be nullptr).
// Phantom columns (p0+p >= P) stay zero so fused stats remain clean.
// ---------------------------------------------------------------------------
template<int TCN>
__global__ __launch_bounds__(256) void sgemm3(
    const float* __restrict__ X, const float* __restrict__ W,
    const float* __restrict__ bias, float* __restrict__ Y,
    int CIN, int COUT, float* __restrict__ stats)
{
    const int P  = PP;
    const int n  = blockIdx.z;
    const int m0 = blockIdx.y * 64;
    const int p0 = blockIdx.x * 256;
    const float* Xn = X + (size_t)n * (TCN ? 64 : CIN) * P;
    float*       Yn = Y + (size_t)n * COUT * P;

    __shared__ __align__(16) float As[2][16][64];
    __shared__ __align__(16) float Bs[2][16][260];

    float acc[8][8];
    #pragma unroll
    for (int i = 0; i < 8; i++)
        #pragma unroll
        for (int j = 0; j < 8; j++) acc[i][j] = 0.f;

    const int tx = threadIdx.x & 31;   // column group (8 cols), full warp
    const int ty = threadIdx.x >> 5;   // row group (8 rows), = warp id

    const int nk = CIN / 16;

    float  pa[4];
    float4 pbv[4];    // non-TCN staging (16 floats)
    float  pbs[16];   // TCN staging

    // ---- initial load of tile 0 ----
    {
        #pragma unroll
        for (int i = 0; i < 4; i++) {
            int idx = threadIdx.x + i * 256;   // 0..1023
            int m = idx >> 4, k = idx & 15;
            float w = 0.f;
            if (m0 + m < COUT) w = W[(size_t)(m0 + m) * CIN + k];
            As[0][k][m] = w;
        }
        if (!TCN) {
            #pragma unroll
            for (int i = 0; i < 4; i++) {
                int f = threadIdx.x + i * 256;  // 0..1023 float4 slots
                int k = f >> 6, p = (f & 63) * 4;
                float4 v = make_float4(0.f, 0.f, 0.f, 0.f);
                if (p0 + p < P)
                    v = *(const float4*)&Xn[(size_t)k * P + p0 + p];
                *(float4*)&Bs[0][k][p] = v;
            }
        } else {
            #pragma unroll
            for (int i = 0; i < 16; i++) {
                int idx = threadIdx.x + i * 256;  // 0..4095
                int k = idx >> 8, p = idx & 255;
                int c = k / 7, dt = k % 7;
                int src = p0 + p + (dt - 3) * 25;
                float v = 0.f;
                if ((p0 + p) < P && src >= 0 && src < P)
                    v = Xn[(size_t)c * P + src];
                Bs[0][k][p] = v;
            }
        }
    }
    __syncthreads();

    for (int it = 0; it < nk; it++) {
        const int cur = it & 1;
        const bool more = (it + 1 < nk);
        const int k0n = (it + 1) * 16;

        // ---- issue next tile's global loads into registers ----
        if (more) {
            #pragma unroll
            for (int i = 0; i < 4; i++) {
                int idx = threadIdx.x + i * 256;
                int m = idx >> 4, k = idx & 15;
                float w = 0.f;
                if (m0 + m < COUT) w = W[(size_t)(m0 + m) * CIN + k0n + k];
                pa[i] = w;
            }
            if (!TCN) {
                #pragma unroll
                for (int i = 0; i < 4; i++) {
                    int f = threadIdx.x + i * 256;
                    int k = f >> 6, p = (f & 63) * 4;
                    float4 v = make_float4(0.f, 0.f, 0.f, 0.f);
                    if (p0 + p < P)
                        v = *(const float4*)&Xn[(size_t)(k0n + k) * P + p0 + p];
                    pbv[i] = v;
                }
            } else {
                #pragma unroll
                for (int i = 0; i < 16; i++) {
                    int idx = threadIdx.x + i * 256;
                    int k = idx >> 8, p = idx & 255;
                    int kk = k0n + k;
                    int c = kk / 7, dt = kk % 7;
                    int src = p0 + p + (dt - 3) * 25;
                    float v = 0.f;
                    if ((p0 + p) < P && src >= 0 && src < P)
                        v = Xn[(size_t)c * P + src];
                    pbs[i] = v;
                }
            }
        }

        // ---- compute current tile ----
        #pragma unroll
        for (int k = 0; k < 16; k++) {
            float a[8], b[8];
            *(float4*)a       = *(const float4*)&As[cur][k][ty * 8];
            *(float4*)(a + 4) = *(const float4*)&As[cur][k][ty * 8 + 4];
            *(float4*)b       = *(const float4*)&Bs[cur][k][tx * 8];
            *(float4*)(b + 4) = *(const float4*)&Bs[cur][k][tx * 8 + 4];
            #pragma unroll
            for (int i = 0; i < 8; i++)
                #pragma unroll
                for (int j = 0; j < 8; j++) acc[i][j] += a[i] * b[j];
        }

        // ---- store prefetched tile to the other buffer ----
        if (more) {
            const int nxt = 1 - cur;
            #pragma unroll
            for (int i = 0; i < 4; i++) {
                int idx = threadIdx.x + i * 256;
                int m = idx >> 4, k = idx & 15;
                As[nxt][k][m] = pa[i];
            }
            if (!TCN) {
                #pragma unroll
                for (int i = 0; i < 4; i++) {
                    int f = threadIdx.x + i * 256;
                    int k = f >> 6, p = (f & 63) * 4;
                    *(float4*)&Bs[nxt][k][p] = pbv[i];
                }
            } else {
                #pragma unroll
                for (int i = 0; i < 16; i++) {
                    int idx = threadIdx.x + i * 256;
                    int k = idx >> 8, p = idx & 255;
                    Bs[nxt][k][p] = pbs[i];
                }
            }
        }
        __syncthreads();
    }

    // ---- epilogue ----
    #pragma unroll
    for (int i = 0; i < 8; i++) {
        int m = m0 + ty * 8 + i;
        if (m < COUT) {
            float bv = bias ? bias[m] : 0.f;
            #pragma unroll
            for (int j = 0; j < 8; j += 4) {
                int p = p0 + tx * 8 + j;
                if (p < P) {
                    float4 v = make_float4(acc[i][j] + bv, acc[i][j + 1] + bv,
                                           acc[i][j + 2] + bv, acc[i][j + 3] + bv);
                    *(float4*)&Yn[(size_t)m * P + p] = v;
                }
            }
        }
    }
    if (stats) {
        #pragma unroll
        for (int i = 0; i < 8; i++) {
            float s = 0.f, s2 = 0.f;
            #pragma unroll
            for (int j = 0; j < 8; j++) { float v = acc[i][j]; s += v; s2 += v * v; }
            #pragma unroll
            for (int o = 16; o > 0; o >>= 1) {
                s  += __shfl_down_sync(0xffffffffu, s,  o);
                s2 += __shfl_down_sync(0xffffffffu, s2, o);
            }
            if (tx == 0) {
                int m = m0 + ty * 8 + i;
                if (m < COUT) {
                    atomicAdd(&stats[m], s);
                    atomicAdd(&stats[64 + m], s2);
                }
            }
        }
    }
}

// ---------------------------------------------------------------------------
// Small GEMM for qk_t (P=64 columns only).
// ---------------------------------------------------------------------------
__global__ __launch_bounds__(256) void sgemm_small(
    const float* __restrict__ X, const float* __restrict__ W,
    const float* __restrict__ bias, float* __restrict__ Y,
    int CIN, int COUT, int P)
{
    const int n  = blockIdx.z;
    const int m0 = blockIdx.y * 64;
    const float* Xn = X + (size_t)n * CIN * P;
    float*       Yn = Y + (size_t)n * COUT * P;

    __shared__ float As[16][68];
    __shared__ float Bs[16][68];
    float acc[4][4];
    #pragma unroll
    for (int i = 0; i < 4; i++)
        #pragma unroll
        for (int j = 0; j < 4; j++) acc[i][j] = 0.f;

    const int tx = threadIdx.x & 15;
    const int ty = threadIdx.x >> 4;

    for (int k0 = 0; k0 < CIN; k0 += 16) {
        for (int i = threadIdx.x; i < 64 * 16; i += 256) {
            int m = i >> 4, k = i & 15;
            float w = 0.f;
            if (m0 + m < COUT) w = W[(size_t)(m0 + m) * CIN + k0 + k];
            As[k][m] = w;
        }
        for (int i = threadIdx.x; i < 16 * 64; i += 256) {
            int k = i >> 6, p = i & 63;
            Bs[k][p] = (p < P) ? Xn[(size_t)(k0 + k) * P + p] : 0.f;
        }
        __syncthreads();
        #pragma unroll
        for (int k = 0; k < 16; k++) {
            float a[4], b[4];
            #pragma unroll
            for (int i = 0; i < 4; i++) a[i] = As[k][ty * 4 + i];
            #pragma unroll
            for (int j = 0; j < 4; j++) b[j] = Bs[k][tx * 4 + j];
            #pragma unroll
            for (int i = 0; i < 4; i++)
                #pragma unroll
                for (int j = 0; j < 4; j++) acc[i][j] += a[i] * b[j];
        }
        __syncthreads();
    }
    #pragma unroll
    for (int i = 0; i < 4; i++) {
        int m = m0 + ty * 4 + i;
        if (m < COUT) {
            float bv = bias ? bias[m] : 0.f;
            #pragma unroll
            for (int j = 0; j < 4; j++) {
                int p = tx * 4 + j;
                if (p < P) Yn[(size_t)m * P + p] = acc[i][j] + bv;
            }
        }
    }
}

// ---------------------------------------------------------------------------
// Fused spatial attention + apply: one block per (n,t).
// ---------------------------------------------------------------------------
__global__ __launch_bounds__(256) void spatial_fused(
    const float* __restrict__ x, const float* __restrict__ qk,
    const float* __restrict__ att0, const float* __restrict__ alphas,
    float* __restrict__ y)
{
    int b = blockIdx.x;
    int t = b % TT; int n = b / TT;
    __shared__ float qs[3][16][25];
    __shared__ float ks[3][16][25];
    __shared__ float xs[25][68];       // [u][c]
    __shared__ float as[3][25][26];    // [s][u][v]

    const float* base = qk + (size_t)n * 96 * PP + t * VV;
    for (int i = threadIdx.x; i < 48 * 25; i += 256) {
        int c = i / 25, u = i % 25;
        qs[c >> 4][c & 15][u] = base[(size_t)c * PP + u];
        ks[c >> 4][c & 15][u] = base[(size_t)(48 + c) * PP + u];
    }
    const float* xb = x + (size_t)n * CC * PP + t * VV;
    for (int i = threadIdx.x; i < 64 * 25; i += 256) {
        int c = i / 25, u = i % 25;
        xs[u][c] = xb[(size_t)c * PP + u];
    }
    __syncthreads();

    for (int i = threadIdx.x; i < 3 * 625; i += 256) {
        int s = i / 625, r = i % 625;
        int u = r / 25, v = r % 25;
        float d = 0.f;
        #pragma unroll
        for (int c = 0; c < 16; c++) d += qs[s][c][u] * ks[s][c][v];
        as[s][u][v] = att0[(size_t)s * 625 + r] + tanhf(d * (1.f / 16.f)) * alphas[s];
    }
    __syncthreads();

    if (threadIdx.x >= 240) return;
    int s  = threadIdx.x / 80;
    int r  = threadIdx.x % 80;
    int cg = r / 5;
    int vg = r % 5;
    float acc[4][5];
    #pragma unroll
    for (int i = 0; i < 4; i++)
        #pragma unroll
        for (int j = 0; j < 5; j++) acc[i][j] = 0.f;
    #pragma unroll
    for (int u = 0; u < 25; u++) {
        float a[4], bb[5];
        #pragma unroll
        for (int i = 0; i < 4; i++) a[i] = xs[u][cg * 4 + i];
        #pragma unroll
        for (int j = 0; j < 5; j++) bb[j] = as[s][u][vg * 5 + j];
        #pragma unroll
        for (int i = 0; i < 4; i++)
            #pragma unroll
            for (int j = 0; j < 5; j++) acc[i][j] += a[i] * bb[j];
    }
    float* yb = y + (size_t)n * 192 * PP + t * VV;
    #pragma unroll
    for (int i = 0; i < 4; i++) {
        float* yp = yb + (size_t)(s * 64 + cg * 4 + i) * PP + vg * 5;
        #pragma unroll
        for (int j = 0; j < 5; j++) yp[j] = acc[i][j];
    }
}

__global__ void zero_stats_kernel(float* s)
{
    int i = blockIdx.x * blockDim.x + threadIdx.x;
    if (i < 5 * 128) s[i] = 0.f;
}

// out = leaky( res + gamma_c*(conv-mu_c)*rsqrt(var_c+eps) + beta_c ), float4
__global__ __launch_bounds__(256) void bn_apply(
    const float4* __restrict__ conv, const float4* __restrict__ res,
    const float* __restrict__ gamma, const float* __restrict__ beta,
    const float* __restrict__ stats, float4* __restrict__ out)
{
    size_t i = (size_t)blockIdx.x * blockDim.x + threadIdx.x;
    const size_t TOT4 = (size_t)NB * CC * PP / 4;
    if (i >= TOT4) return;
    int c = (int)((i / (PP / 4)) & 63);
    float mu  = stats[c] * (1.f / (float)NTV);
    float var = stats[64 + c] * (1.f / (float)NTV) - mu * mu;
    float g = gamma[c] * rsqrtf(var + 1e-5f);
    float sh = beta[c] - mu * g;
    float4 cv = conv[i], rv = res[i], o;
    float v;
    v = rv.x + cv.x * g + sh; o.x = v > 0.f ? v : 0.1f * v;
    v = rv.y + cv.y * g + sh; o.y = v > 0.f ? v : 0.1f * v;
    v = rv.z + cv.z * g + sh; o.z = v > 0.f ? v : 0.1f * v;
    v = rv.w + cv.w * g + sh; o.w = v > 0.f ? v : 0.1f * v;
    out[i] = o;
}

// ---------------------------------------------------------------------------
// Temporal path
// ---------------------------------------------------------------------------
__global__ void mean_v_kernel(const float* __restrict__ X, float* __restrict__ xb)
{
    int i = blockIdx.x * blockDim.x + threadIdx.x;  // over N*C*T
    if (i >= NB * CC * TT) return;
    const float* p = X + (size_t)i * VV;
    float s = 0.f;
    #pragma unroll
    for (int v = 0; v < VV; v++) s += p[v];
    xb[i] = s * (1.f / (float)VV);
}

__global__ __launch_bounds__(256) void temporal_att(
    const float* __restrict__ qkt, const float* __restrict__ alphaf,
    const float* __restrict__ alphab, float* __restrict__ attt)
{
    int b = blockIdx.x;
    int slot = b & 3; int n = b >> 2;
    int dir = slot >> 1, s = slot & 1;
    int qg = (dir == 0) ? s : 2 + s;
    int kg = (dir == 0) ? 4 + s : 6 + s;
    __shared__ float qs[16][64], ks2[16][64];
    const float* base = qkt + (size_t)n * 128 * TT;
    for (int i = threadIdx.x; i < 16 * 64; i += 256) {
        int c = i >> 6, t = i & 63;
        qs [c][t] = base[(size_t)(qg * 16 + c) * TT + t];
        ks2[c][t] = base[(size_t)(kg * 16 + c) * TT + t];
    }
    __syncthreads();
    float alpha = (dir == 0) ? alphaf[s] : alphab[s];
    float* outp = attt + ((size_t)n * 4 + slot) * TT * TT;
    for (int i = threadIdx.x; i < TT * TT; i += 256) {
        int t = i >> 6, q = i & 63;
        bool keep = (dir == 0) ? (t >= q) : (q >= t);
        float d = 0.f;
        #pragma unroll
        for (int c = 0; c < 16; c++) d += qs[c][t] * ks2[c][q];
        outp[i] = keep ? tanhf(d * (1.f / 16.f)) * alpha : 0.f;
    }
}

// z[n, chbase+c, q, v] = sum_t tin[n,c,t,v] * att[t,q]
__global__ __launch_bounds__(256) void temporal_apply(
    const float* __restrict__ tin, const float* __restrict__ attt,
    float* __restrict__ z)
{
    int b = blockIdx.x;
    int slot = b & 3; int n = b >> 2;
    int dir = slot >> 1, s = slot & 1;
    int chbase = dir * 128 + s * 64;
    __shared__ float as[64][65];
    const float* ap = attt + ((size_t)n * 4 + slot) * TT * TT;
    for (int i = threadIdx.x; i < TT * TT; i += 256) as[i >> 6][i & 63] = ap[i];
    __syncthreads();
    const float* tb = tin + (size_t)n * CC * PP;
    float*       zb = z   + (size_t)n * 256 * PP;
    for (int r = threadIdx.x; r < CC * VV; r += 256) {
        int c = r / 25, v = r % 25;
        float acc[64];
        #pragma unroll
        for (int q = 0; q < 64; q++) acc[q] = 0.f;
        const float* tp = tb + (size_t)c * PP + v;
        for (int t = 0; t < 64; t++) {
            float a = tp[t * 25];
            #pragma unroll
            for (int q = 0; q < 64; q++) acc[q] += a * as[t][q];
        }
        float* zp = zb + (size_t)(chbase + c) * PP + v;
        #pragma unroll
        for (int q = 0; q < 64; q++) zp[q * 25] = acc[q];
    }
}

// ---------------------------------------------------------------------------
// Launcher
// ---------------------------------------------------------------------------
static float* sym(const void* symbol)
{
    void* p = nullptr;
    cudaGetSymbolAddress(&p, symbol);
    return (float*)p;
}

extern "C" void kernel_launch(void* const* d_in, const int* in_sizes, int n_in,
                              void* d_out, int out_size)
{
    const float* x       = (const float*)d_in[0];
    const float* att0s   = (const float*)d_in[1];
    const float* alphas  = (const float*)d_in[2];
    const float* W_qk_s  = (const float*)d_in[3];
    const float* b_qk_s  = (const float*)d_in[4];
    const float* W_outs  = (const float*)d_in[5];
    const float* g_outs  = (const float*)d_in[7];
    const float* be_outs = (const float*)d_in[8];
    const float* W_ffs   = (const float*)d_in[9];
    const float* g_ffs   = (const float*)d_in[11];
    const float* be_ffs  = (const float*)d_in[12];
    const float* W_qk_t  = (const float*)d_in[13];
    const float* b_qk_t  = (const float*)d_in[14];
    const float* al_f    = (const float*)d_in[15];
    const float* al_b    = (const float*)d_in[16];
    const float* W_outt  = (const float*)d_in[17];
    const float* g_outt  = (const float*)d_in[19];
    const float* be_outt = (const float*)d_in[20];
    const float* W_fft   = (const float*)d_in[21];
    const float* g_fft   = (const float*)d_in[23];
    const float* be_fft  = (const float*)d_in[24];
    const float* W_tcn   = (const float*)d_in[25];
    const float* g_tcn   = (const float*)d_in[27];
    const float* be_tcn  = (const float*)d_in[28];
    float* out = (float*)d_out;

    float* p_qk   = sym(g_qk);
    float* p_y    = sym(g_y);
    float* p_conv = sym(g_conv);
    float* p_sout = sym(g_sout);
    float* p_b1   = sym(g_b1);
    float* p_b2   = sym(g_b2);
    float* p_xbar = sym(g_xbar);
    float* p_qkt  = sym(g_qkt);
    float* p_attt = sym(g_attt);
    float* p_z    = sym(g_z);
    float* p_st   = sym(g_stats);

    const size_t TOT = (size_t)NB * CC * PP;
    const int EW_BLOCKS4 = (int)((TOT / 4 + 255) / 256);
    const dim3 G7(7, 1, NB);

    zero_stats_kernel<<<3, 256>>>(p_st);

    // --- spatial attention (fused att + apply) ---
    sgemm3<0><<<dim3(7, 2, NB), 256>>>(x, W_qk_s, b_qk_s, p_qk, 64, 96, nullptr);
    spatial_fused<<<NB * TT, 256>>>(x, p_qk, att0s, alphas, p_y);

    // y = BN(conv(y, W_outs)); y = leaky(x + y)   [bias cancels in BN]
    sgemm3<0><<<G7, 256>>>(p_y, W_outs, nullptr, p_conv, 192, 64, p_st + 0);
    bn_apply<<<EW_BLOCKS4, 256>>>((const float4*)p_conv, (const float4*)x,
                                  g_outs, be_outs, p_st + 0, (float4*)p_b1);

    // y = BN(conv(y, W_ffs)); s_out = leaky(x + y)
    sgemm3<0><<<G7, 256>>>(p_b1, W_ffs, nullptr, p_conv, 64, 64, p_st + 128);
    bn_apply<<<EW_BLOCKS4, 256>>>((const float4*)p_conv, (const float4*)x,
                                  g_ffs, be_ffs, p_st + 128, (float4*)p_sout);

    // --- temporal attention ---
    mean_v_kernel<<<(NB * CC * TT + 255) / 256, 256>>>(p_sout, p_xbar);
    sgemm_small<<<dim3(1, 2, NB), 256>>>(p_xbar, W_qk_t, b_qk_t, p_qkt, 64, 128, TT);
    temporal_att<<<NB * 4, 256>>>(p_qkt, al_f, al_b, p_attt);
    temporal_apply<<<NB * 4, 256>>>(p_sout, p_attt, p_z);

    // z = BN(conv(z, W_outt)); z = leaky(t_in + z)
    sgemm3<0><<<G7, 256>>>(p_z, W_outt, nullptr, p_conv, 256, 64, p_st + 256);
    bn_apply<<<EW_BLOCKS4, 256>>>((const float4*)p_conv, (const float4*)p_sout,
                                  g_outt, be_outt, p_st + 256, (float4*)p_b1);

    // z = BN(conv(z, W_fft)); z = leaky(t_in + z)
    sgemm3<0><<<G7, 256>>>(p_b1, W_fft, nullptr, p_conv, 64, 64, p_st + 384);
    bn_apply<<<EW_BLOCKS4, 256>>>((const float4*)p_conv, (const float4*)p_sout,
                                  g_fft, be_fft, p_st + 384, (float4*)p_b2);

    // --- TCN as K=448 GEMM (k = c*7+dt, shifted B rows) ---
    sgemm3<1><<<G7, 256>>>(p_b2, W_tcn, nullptr, p_conv, 448, 64, p_st + 512);
    bn_apply<<<EW_BLOCKS4, 256>>>((const float4*)p_conv, (const float4*)p_b2,
                                  g_tcn, be_tcn, p_st + 512, (float4*)out);
}

// round 9
// speedup vs baseline: 1.8061x; 1.1072x over previous
#include <cuda_runtime.h>
#include <cuda_bf16.h>
#include <math.h>
#include <cstdint>

// ---------------------------------------------------------------------------
// Problem constants
// ---------------------------------------------------------------------------
#define NB   128          // batch N
#define CC   64           // channels C = O
#define TT   64           // T
#define VV   25           // V
#define PP   (TT*VV)      // 1600 positions per (n, channel)
#define SS   3            // spatial heads
#define NTV  (NB*TT*VV)   // 204800 samples per channel for BN

// ---------------------------------------------------------------------------
// Scratch (device globals; no allocation allowed)
// ---------------------------------------------------------------------------
__device__ float g_qk  [ (size_t)NB*96*PP ];        // spatial qk conv out
__device__ float g_y   [ (size_t)NB*192*PP ];       // spatial attended
__device__ float g_conv[ (size_t)NB*CC*PP ];        // generic conv output
__device__ float g_sout[ (size_t)NB*CC*PP ];        // s_out == t_in
__device__ float g_b1  [ (size_t)NB*CC*PP ];
__device__ float g_b2  [ (size_t)NB*CC*PP ];
__device__ float g_xbar[ (size_t)NB*CC*TT ];        // mean over V
__device__ float g_qkt [ (size_t)NB*128*TT ];
__device__ float g_attt[ (size_t)NB*4*TT*TT ];      // 4 slots: f0,f1,b0,b1
__device__ float g_z   [ (size_t)NB*256*PP ];       // temporal attended
__device__ float g_stats[5*128];                    // 5 BNs x (sum[64], sumsq[64])

// ---------------------------------------------------------------------------
// cp.async helpers
// ---------------------------------------------------------------------------
__device__ __forceinline__ unsigned int smem_u32(const void* p)
{
    return (unsigned int)__cvta_generic_to_shared(p);
}
__device__ __forceinline__ void cp16(unsigned int dst, const void* src, int sbytes)
{
    asm volatile("cp.async.cg.shared.global [%0], [%1], 16, %2;"
                 :: "r"(dst), "l"(src), "r"(sbytes));
}
__device__ __forceinline__ void cp4(unsigned int dst, const void* src, int sbytes)
{
    asm volatile("cp.async.ca.shared.global [%0], [%1], 4, %2;"
                 :: "r"(dst), "l"(src), "r"(sbytes));
}
__device__ __forceinline__ void cp_commit()
{
    asm volatile("cp.async.commit_group;");
}
template<int N>
__device__ __forceinline__ void cp_wait()
{
    asm volatile("cp.async.wait_group %0;" :: "n"(N));
}

// ---------------------------------------------------------------------------
// Balanced-ratio GEMM for 1x1 convs (and the TCN as a K=448 GEMM).
//   Y[n][m][p] = sum_k A[m][k] * B[k][p]      (per n)
// TCN==0: A=W (COUT x CIN), B[k][p] = X[n][k][p]
// TCN==1: A=W_tcn flattened (64 x 448), k=(c*7+dt),
//         B[k][p] = X[n][c][p + (dt-3)*25] with zero fill out of range.
// Tile: BM=64, BN=256, BK=16; 256 threads; 8x8 microtile.
// B tiles fetched via cp.async directly into double-buffered smem (no
// register staging -> regs fit 2 CTAs/SM). A uses 4-reg staging.
// grid: (7, ceil(COUT/64), NB)
// If stats != nullptr, fuses per-channel sum/sumsq (bias must be nullptr).
// Phantom columns (p0+p >= P) stay zero (cp.async zfill) -> clean stats.
// ---------------------------------------------------------------------------
template<int TCN>
__global__ __launch_bounds__(256, 2) void sgemm3(
    const float* __restrict__ X, const float* __restrict__ W,
    const float* __restrict__ bias, float* __restrict__ Y,
    int CIN, int COUT, float* __restrict__ stats)
{
    const int P  = PP;
    const int n  = blockIdx.z;
    const int m0 = blockIdx.y * 64;
    const int p0 = blockIdx.x * 256;
    const float* Xn = X + (size_t)n * (TCN ? 64 : CIN) * P;
    float*       Yn = Y + (size_t)n * COUT * P;

    __shared__ __align__(16) float As[2][16][64];
    __shared__ __align__(16) float Bs[2][16][260];

    float acc[8][8];
    #pragma unroll
    for (int i = 0; i < 8; i++)
        #pragma unroll
        for (int j = 0; j < 8; j++) acc[i][j] = 0.f;

    const int tx = threadIdx.x & 31;   // column group (8 cols), full warp
    const int ty = threadIdx.x >> 5;   // row group (8 rows), = warp id

    const int nk = CIN / 16;
    float pa[4];

    // ---- issue B tile for k-tile `kt` into buffer `buf` via cp.async ----
    auto issueB = [&](int kt, int buf) {
        const int k0 = kt * 16;
        if (!TCN) {
            #pragma unroll
            for (int i = 0; i < 4; i++) {
                int f = threadIdx.x + i * 256;      // 0..1023 float4 slots
                int k = f >> 6, p = (f & 63) * 4;
                bool ok = (p0 + p) < P;
                const float* src = ok ? &Xn[(size_t)(k0 + k) * P + p0 + p] : Xn;
                cp16(smem_u32(&Bs[buf][k][p]), src, ok ? 16 : 0);
            }
        } else {
            #pragma unroll
            for (int i = 0; i < 16; i++) {
                int idx = threadIdx.x + i * 256;    // 0..4095
                int k = idx >> 8, p = idx & 255;
                int kk = k0 + k;
                int c = kk / 7, dt = kk % 7;
                int src = p0 + p + (dt - 3) * 25;
                bool ok = (p0 + p) < P && src >= 0 && src < P;
                const float* sp = ok ? &Xn[(size_t)c * P + src] : Xn;
                cp4(smem_u32(&Bs[buf][k][p]), sp, ok ? 4 : 0);
            }
        }
        cp_commit();
    };

    // ---- prologue: tile 0 ----
    #pragma unroll
    for (int i = 0; i < 4; i++) {
        int idx = threadIdx.x + i * 256;   // 0..1023
        int m = idx >> 4, k = idx & 15;
        float w = 0.f;
        if (m0 + m < COUT) w = W[(size_t)(m0 + m) * CIN + k];
        As[0][k][m] = w;
    }
    issueB(0, 0);

    for (int it = 0; it < nk; it++) {
        const int cur = it & 1;
        const int nxt = 1 - cur;
        const bool more = (it + 1 < nk);

        if (more) {
            issueB(it + 1, nxt);
            const int k0n = (it + 1) * 16;
            #pragma unroll
            for (int i = 0; i < 4; i++) {
                int idx = threadIdx.x + i * 256;
                int m = idx >> 4, k = idx & 15;
                float w = 0.f;
                if (m0 + m < COUT) w = W[(size_t)(m0 + m) * CIN + k0n + k];
                pa[i] = w;
            }
        }

        if (more) cp_wait<1>(); else cp_wait<0>();
        __syncthreads();

        // ---- compute current tile ----
        #pragma unroll
        for (int k = 0; k < 16; k++) {
            float a[8], b[8];
            *(float4*)a       = *(const float4*)&As[cur][k][ty * 8];
            *(float4*)(a + 4) = *(const float4*)&As[cur][k][ty * 8 + 4];
            *(float4*)b       = *(const float4*)&Bs[cur][k][tx * 8];
            *(float4*)(b + 4) = *(const float4*)&Bs[cur][k][tx * 8 + 4];
            #pragma unroll
            for (int i = 0; i < 8; i++)
                #pragma unroll
                for (int j = 0; j < 8; j++) acc[i][j] += a[i] * b[j];
        }

        if (more) {
            #pragma unroll
            for (int i = 0; i < 4; i++) {
                int idx = threadIdx.x + i * 256;
                int m = idx >> 4, k = idx & 15;
                As[nxt][k][m] = pa[i];
            }
        }
        __syncthreads();
    }

    // ---- epilogue ----
    #pragma unroll
    for (int i = 0; i < 8; i++) {
        int m = m0 + ty * 8 + i;
        if (m < COUT) {
            float bv = bias ? bias[m] : 0.f;
            #pragma unroll
            for (int j = 0; j < 8; j += 4) {
                int p = p0 + tx * 8 + j;
                if (p < P) {
                    float4 v = make_float4(acc[i][j] + bv, acc[i][j + 1] + bv,
                                           acc[i][j + 2] + bv, acc[i][j + 3] + bv);
                    *(float4*)&Yn[(size_t)m * P + p] = v;
                }
            }
        }
    }
    if (stats) {
        #pragma unroll
        for (int i = 0; i < 8; i++) {
            float s = 0.f, s2 = 0.f;
            #pragma unroll
            for (int j = 0; j < 8; j++) { float v = acc[i][j]; s += v; s2 += v * v; }
            #pragma unroll
            for (int o = 16; o > 0; o >>= 1) {
                s  += __shfl_down_sync(0xffffffffu, s,  o);
                s2 += __shfl_down_sync(0xffffffffu, s2, o);
            }
            if (tx == 0) {
                int m = m0 + ty * 8 + i;
                if (m < COUT) {
                    atomicAdd(&stats[m], s);
                    atomicAdd(&stats[64 + m], s2);
                }
            }
        }
    }
}

// ---------------------------------------------------------------------------
// Small GEMM for qk_t (P=64 columns only).
// ---------------------------------------------------------------------------
__global__ __launch_bounds__(256) void sgemm_small(
    const float* __restrict__ X, const float* __restrict__ W,
    const float* __restrict__ bias, float* __restrict__ Y,
    int CIN, int COUT, int P)
{
    const int n  = blockIdx.z;
    const int m0 = blockIdx.y * 64;
    const float* Xn = X + (size_t)n * CIN * P;
    float*       Yn = Y + (size_t)n * COUT * P;

    __shared__ float As[16][68];
    __shared__ float Bs[16][68];
    float acc[4][4];
    #pragma unroll
    for (int i = 0; i < 4; i++)
        #pragma unroll
        for (int j = 0; j < 4; j++) acc[i][j] = 0.f;

    const int tx = threadIdx.x & 15;
    const int ty = threadIdx.x >> 4;

    for (int k0 = 0; k0 < CIN; k0 += 16) {
        for (int i = threadIdx.x; i < 64 * 16; i += 256) {
            int m = i >> 4, k = i & 15;
            float w = 0.f;
            if (m0 + m < COUT) w = W[(size_t)(m0 + m) * CIN + k0 + k];
            As[k][m] = w;
        }
        for (int i = threadIdx.x; i < 16 * 64; i += 256) {
            int k = i >> 6, p = i & 63;
            Bs[k][p] = (p < P) ? Xn[(size_t)(k0 + k) * P + p] : 0.f;
        }
        __syncthreads();
        #pragma unroll
        for (int k = 0; k < 16; k++) {
            float a[4], b[4];
            #pragma unroll
            for (int i = 0; i < 4; i++) a[i] = As[k][ty * 4 + i];
            #pragma unroll
            for (int j = 0; j < 4; j++) b[j] = Bs[k][tx * 4 + j];
            #pragma unroll
            for (int i = 0; i < 4; i++)
                #pragma unroll
                for (int j = 0; j < 4; j++) acc[i][j] += a[i] * b[j];
        }
        __syncthreads();
    }
    #pragma unroll
    for (int i = 0; i < 4; i++) {
        int m = m0 + ty * 4 + i;
        if (m < COUT) {
            float bv = bias ? bias[m] : 0.f;
            #pragma unroll
            for (int j = 0; j < 4; j++) {
                int p = tx * 4 + j;
                if (p < P) Yn[(size_t)m * P + p] = acc[i][j] + bv;
            }
        }
    }
}

// ---------------------------------------------------------------------------
// Fused spatial attention + apply: one block per (n,t).
// ---------------------------------------------------------------------------
__global__ __launch_bounds__(256) void spatial_fused(
    const float* __restrict__ x, const float* __restrict__ qk,
    const float* __restrict__ att0, const float* __restrict__ alphas,
    float* __restrict__ y)
{
    int b = blockIdx.x;
    int t = b % TT; int n = b / TT;
    __shared__ float qs[3][16][25];
    __shared__ float ks[3][16][25];
    __shared__ float xs[25][68];       // [u][c]
    __shared__ float as[3][25][26];    // [s][u][v]

    const float* base = qk + (size_t)n * 96 * PP + t * VV;
    for (int i = threadIdx.x; i < 48 * 25; i += 256) {
        int c = i / 25, u = i % 25;
        qs[c >> 4][c & 15][u] = base[(size_t)c * PP + u];
        ks[c >> 4][c & 15][u] = base[(size_t)(48 + c) * PP + u];
    }
    const float* xb = x + (size_t)n * CC * PP + t * VV;
    for (int i = threadIdx.x; i < 64 * 25; i += 256) {
        int c = i / 25, u = i % 25;
        xs[u][c] = xb[(size_t)c * PP + u];
    }
    __syncthreads();

    for (int i = threadIdx.x; i < 3 * 625; i += 256) {
        int s = i / 625, r = i % 625;
        int u = r / 25, v = r % 25;
        float d = 0.f;
        #pragma unroll
        for (int c = 0; c < 16; c++) d += qs[s][c][u] * ks[s][c][v];
        as[s][u][v] = att0[(size_t)s * 625 + r] + tanhf(d * (1.f / 16.f)) * alphas[s];
    }
    __syncthreads();

    if (threadIdx.x >= 240) return;
    int s  = threadIdx.x / 80;
    int r  = threadIdx.x % 80;
    int cg = r / 5;
    int vg = r % 5;
    float acc[4][5];
    #pragma unroll
    for (int i = 0; i < 4; i++)
        #pragma unroll
        for (int j = 0; j < 5; j++) acc[i][j] = 0.f;
    #pragma unroll
    for (int u = 0; u < 25; u++) {
        float a[4], bb[5];
        #pragma unroll
        for (int i = 0; i < 4; i++) a[i] = xs[u][cg * 4 + i];
        #pragma unroll
        for (int j = 0; j < 5; j++) bb[j] = as[s][u][vg * 5 + j];
        #pragma unroll
        for (int i = 0; i < 4; i++)
            #pragma unroll
            for (int j = 0; j < 5; j++) acc[i][j] += a[i] * bb[j];
    }
    float* yb = y + (size_t)n * 192 * PP + t * VV;
    #pragma unroll
    for (int i = 0; i < 4; i++) {
        float* yp = yb + (size_t)(s * 64 + cg * 4 + i) * PP + vg * 5;
        #pragma unroll
        for (int j = 0; j < 5; j++) yp[j] = acc[i][j];
    }
}

__global__ void zero_stats_kernel(float* s)
{
    int i = blockIdx.x * blockDim.x + threadIdx.x;
    if (i < 5 * 128) s[i] = 0.f;
}

// out = leaky( res + gamma_c*(conv-mu_c)*rsqrt(var_c+eps) + beta_c ), float4
__global__ __launch_bounds__(256) void bn_apply(
    const float4* __restrict__ conv, const float4* __restrict__ res,
    const float* __restrict__ gamma, const float* __restrict__ beta,
    const float* __restrict__ stats, float4* __restrict__ out)
{
    size_t i = (size_t)blockIdx.x * blockDim.x + threadIdx.x;
    const size_t TOT4 = (size_t)NB * CC * PP / 4;
    if (i >= TOT4) return;
    int c = (int)((i / (PP / 4)) & 63);
    float mu  = stats[c] * (1.f / (float)NTV);
    float var = stats[64 + c] * (1.f / (float)NTV) - mu * mu;
    float g = gamma[c] * rsqrtf(var + 1e-5f);
    float sh = beta[c] - mu * g;
    float4 cv = conv[i], rv = res[i], o;
    float v;
    v = rv.x + cv.x * g + sh; o.x = v > 0.f ? v : 0.1f * v;
    v = rv.y + cv.y * g + sh; o.y = v > 0.f ? v : 0.1f * v;
    v = rv.z + cv.z * g + sh; o.z = v > 0.f ? v : 0.1f * v;
    v = rv.w + cv.w * g + sh; o.w = v > 0.f ? v : 0.1f * v;
    out[i] = o;
}

// ---------------------------------------------------------------------------
// Temporal path
// ---------------------------------------------------------------------------
__global__ void mean_v_kernel(const float* __restrict__ X, float* __restrict__ xb)
{
    int i = blockIdx.x * blockDim.x + threadIdx.x;  // over N*C*T
    if (i >= NB * CC * TT) return;
    const float* p = X + (size_t)i * VV;
    float s = 0.f;
    #pragma unroll
    for (int v = 0; v < VV; v++) s += p[v];
    xb[i] = s * (1.f / (float)VV);
}

__global__ __launch_bounds__(256) void temporal_att(
    const float* __restrict__ qkt, const float* __restrict__ alphaf,
    const float* __restrict__ alphab, float* __restrict__ attt)
{
    int b = blockIdx.x;
    int slot = b & 3; int n = b >> 2;
    int dir = slot >> 1, s = slot & 1;
    int qg = (dir == 0) ? s : 2 + s;
    int kg = (dir == 0) ? 4 + s : 6 + s;
    __shared__ float qs[16][64], ks2[16][64];
    const float* base = qkt + (size_t)n * 128 * TT;
    for (int i = threadIdx.x; i < 16 * 64; i += 256) {
        int c = i >> 6, t = i & 63;
        qs [c][t] = base[(size_t)(qg * 16 + c) * TT + t];
        ks2[c][t] = base[(size_t)(kg * 16 + c) * TT + t];
    }
    __syncthreads();
    float alpha = (dir == 0) ? alphaf[s] : alphab[s];
    float* outp = attt + ((size_t)n * 4 + slot) * TT * TT;
    for (int i = threadIdx.x; i < TT * TT; i += 256) {
        int t = i >> 6, q = i & 63;
        bool keep = (dir == 0) ? (t >= q) : (q >= t);
        float d = 0.f;
        #pragma unroll
        for (int c = 0; c < 16; c++) d += qs[c][t] * ks2[c][q];
        outp[i] = keep ? tanhf(d * (1.f / 16.f)) * alpha : 0.f;
    }
}

// z[n, chbase+c, q, v] = sum_t tin[n,c,t,v] * att[t,q]
__global__ __launch_bounds__(256) void temporal_apply(
    const float* __restrict__ tin, const float* __restrict__ attt,
    float* __restrict__ z)
{
    int b = blockIdx.x;
    int slot = b & 3; int n = b >> 2;
    int dir = slot >> 1, s = slot & 1;
    int chbase = dir * 128 + s * 64;
    __shared__ float as[64][65];
    const float* ap = attt + ((size_t)n * 4 + slot) * TT * TT;
    for (int i = threadIdx.x; i < TT * TT; i += 256) as[i >> 6][i & 63] = ap[i];
    __syncthreads();
    const float* tb = tin + (size_t)n * CC * PP;
    float*       zb = z   + (size_t)n * 256 * PP;
    for (int r = threadIdx.x; r < CC * VV; r += 256) {
        int c = r / 25, v = r % 25;
        float acc[64];
        #pragma unroll
        for (int q = 0; q < 64; q++) acc[q] = 0.f;
        const float* tp = tb + (size_t)c * PP + v;
        for (int t = 0; t < 64; t++) {
            float a = tp[t * 25];
            #pragma unroll
            for (int q = 0; q < 64; q++) acc[q] += a * as[t][q];
        }
        float* zp = zb + (size_t)(chbase + c) * PP + v;
        #pragma unroll
        for (int q = 0; q < 64; q++) zp[q * 25] = acc[q];
    }
}

// ---------------------------------------------------------------------------
// Launcher
// ---------------------------------------------------------------------------
static float* sym(const void* symbol)
{
    void* p = nullptr;
    cudaGetSymbolAddress(&p, symbol);
    return (float*)p;
}

extern "C" void kernel_launch(void* const* d_in, const int* in_sizes, int n_in,
                              void* d_out, int out_size)
{
    const float* x       = (const float*)d_in[0];
    const float* att0s   = (const float*)d_in[1];
    const float* alphas  = (const float*)d_in[2];
    const float* W_qk_s  = (const float*)d_in[3];
    const float* b_qk_s  = (const float*)d_in[4];
    const float* W_outs  = (const float*)d_in[5];
    const float* g_outs  = (const float*)d_in[7];
    const float* be_outs = (const float*)d_in[8];
    const float* W_ffs   = (const float*)d_in[9];
    const float* g_ffs   = (const float*)d_in[11];
    const float* be_ffs  = (const float*)d_in[12];
    const float* W_qk_t  = (const float*)d_in[13];
    const float* b_qk_t  = (const float*)d_in[14];
    const float* al_f    = (const float*)d_in[15];
    const float* al_b    = (const float*)d_in[16];
    const float* W_outt  = (const float*)d_in[17];
    const float* g_outt  = (const float*)d_in[19];
    const float* be_outt = (const float*)d_in[20];
    const float* W_fft   = (const float*)d_in[21];
    const float* g_fft   = (const float*)d_in[23];
    const float* be_fft  = (const float*)d_in[24];
    const float* W_tcn   = (const float*)d_in[25];
    const float* g_tcn   = (const float*)d_in[27];
    const float* be_tcn  = (const float*)d_in[28];
    float* out = (float*)d_out;

    float* p_qk   = sym(g_qk);
    float* p_y    = sym(g_y);
    float* p_conv = sym(g_conv);
    float* p_sout = sym(g_sout);
    float* p_b1   = sym(g_b1);
    float* p_b2   = sym(g_b2);
    float* p_xbar = sym(g_xbar);
    float* p_qkt  = sym(g_qkt);
    float* p_attt = sym(g_attt);
    float* p_z    = sym(g_z);
    float* p_st   = sym(g_stats);

    const size_t TOT = (size_t)NB * CC * PP;
    const int EW_BLOCKS4 = (int)((TOT / 4 + 255) / 256);
    const dim3 G7(7, 1, NB);

    zero_stats_kernel<<<3, 256>>>(p_st);

    // --- spatial attention (fused att + apply) ---
    sgemm3<0><<<dim3(7, 2, NB), 256>>>(x, W_qk_s, b_qk_s, p_qk, 64, 96, nullptr);
    spatial_fused<<<NB * TT, 256>>>(x, p_qk, att0s, alphas, p_y);

    // y = BN(conv(y, W_outs)); y = leaky(x + y)   [bias cancels in BN]
    sgemm3<0><<<G7, 256>>>(p_y, W_outs, nullptr, p_conv, 192, 64, p_st + 0);
    bn_apply<<<EW_BLOCKS4, 256>>>((const float4*)p_conv, (const float4*)x,
                                  g_outs, be_outs, p_st + 0, (float4*)p_b1);

    // y = BN(conv(y, W_ffs)); s_out = leaky(x + y)
    sgemm3<0><<<G7, 256>>>(p_b1, W_ffs, nullptr, p_conv, 64, 64, p_st + 128);
    bn_apply<<<EW_BLOCKS4, 256>>>((const float4*)p_conv, (const float4*)x,
                                  g_ffs, be_ffs, p_st + 128, (float4*)p_sout);

    // --- temporal attention ---
    mean_v_kernel<<<(NB * CC * TT + 255) / 256, 256>>>(p_sout, p_xbar);
    sgemm_small<<<dim3(1, 2, NB), 256>>>(p_xbar, W_qk_t, b_qk_t, p_qkt, 64, 128, TT);
    temporal_att<<<NB * 4, 256>>>(p_qkt, al_f, al_b, p_attt);
    temporal_apply<<<NB * 4, 256>>>(p_sout, p_attt, p_z);

    // z = BN(conv(z, W_outt)); z = leaky(t_in + z)
    sgemm3<0><<<G7, 256>>>(p_z, W_outt, nullptr, p_conv, 256, 64, p_st + 256);
    bn_apply<<<EW_BLOCKS4, 256>>>((const float4*)p_conv, (const float4*)p_sout,
                                  g_outt, be_outt, p_st + 256, (float4*)p_b1);

    // z = BN(conv(z, W_fft)); z = leaky(t_in + z)
    sgemm3<0><<<G7, 256>>>(p_b1, W_fft, nullptr, p_conv, 64, 64, p_st + 384);
    bn_apply<<<EW_BLOCKS4, 256>>>((const float4*)p_conv, (const float4*)p_sout,
                                  g_fft, be_fft, p_st + 384, (float4*)p_b2);

    // --- TCN as K=448 GEMM (k = c*7+dt, shifted B rows) ---
    sgemm3<1><<<G7, 256>>>(p_b2, W_tcn, nullptr, p_conv, 448, 64, p_st + 512);
    bn_apply<<<EW_BLOCKS4, 256>>>((const float4*)p_conv, (const float4*)p_b2,
                                  g_tcn, be_tcn, p_st + 512, (float4*)out);
}

// round 10
// speedup vs baseline: 1.8558x; 1.0275x over previous
#include <cuda_runtime.h>
#include <cuda_bf16.h>
#include <math.h>
#include <cstdint>

// ---------------------------------------------------------------------------
// Problem constants
// ---------------------------------------------------------------------------
#define NB   128          // batch N
#define CC   64           // channels C = O
#define TT   64           // T
#define VV   25           // V
#define PP   (TT*VV)      // 1600 positions per (n, channel)
#define SS   3            // spatial heads
#define NTV  (NB*TT*VV)   // 204800 samples per channel for BN

// ---------------------------------------------------------------------------
// Scratch (device globals; no allocation allowed)
// ---------------------------------------------------------------------------
__device__ float g_qk  [ (size_t)NB*96*PP ];        // spatial qk conv out
__device__ float g_y   [ (size_t)NB*192*PP ];       // spatial attended
__device__ float g_conv[ (size_t)NB*CC*PP ];        // generic conv output
__device__ float g_sout[ (size_t)NB*CC*PP ];        // s_out == t_in
__device__ float g_b1  [ (size_t)NB*CC*PP ];
__device__ float g_b2  [ (size_t)NB*CC*PP ];
__device__ float g_xbar[ (size_t)NB*CC*TT ];        // mean over V
__device__ float g_qkt [ (size_t)NB*128*TT ];
__device__ float g_attt[ (size_t)NB*4*TT*TT ];      // 4 slots: f0,f1,b0,b1
__device__ float g_z   [ (size_t)NB*256*PP ];       // temporal attended
__device__ float g_stats[5*128];                    // 5 BNs x (sum[64], sumsq[64])

// ---------------------------------------------------------------------------
// cp.async helpers
// ---------------------------------------------------------------------------
__device__ __forceinline__ unsigned int smem_u32(const void* p)
{
    return (unsigned int)__cvta_generic_to_shared(p);
}
__device__ __forceinline__ void cp16(unsigned int dst, const void* src, int sbytes)
{
    asm volatile("cp.async.cg.shared.global [%0], [%1], 16, %2;"
                 :: "r"(dst), "l"(src), "r"(sbytes));
}
__device__ __forceinline__ void cp4(unsigned int dst, const void* src, int sbytes)
{
    asm volatile("cp.async.ca.shared.global [%0], [%1], 4, %2;"
                 :: "r"(dst), "l"(src), "r"(sbytes));
}
__device__ __forceinline__ void cp_commit()
{
    asm volatile("cp.async.commit_group;");
}
template<int N>
__device__ __forceinline__ void cp_wait()
{
    asm volatile("cp.async.wait_group %0;" :: "n"(N));
}

// ---------------------------------------------------------------------------
// Balanced-ratio GEMM for 1x1 convs (and the TCN as a K=448 GEMM).
//   Y[n][m][p] = sum_k A[m][k] * B[k][p]      (per n)
// TCN==0: A=W (COUT x CIN), B[k][p] = X[n][k][p]
// TCN==1: A=W_tcn flattened (64 x 448), k=(c*7+dt),
//         B[k][p] = X[n][c][p + (dt-3)*25] with zero fill out of range.
// Tile: BM=64, BN=256, BK=16; 256 threads; 8x8 microtile with SPLIT column
// mapping: thread covers columns [tx*4, tx*4+4) and [128+tx*4, 128+tx*4+4).
// This makes both B LDS.128 reads lane-contiguous (16B stride, 4 wavefronts,
// conflict-free) instead of 32B stride (8 wavefronts, 2-way conflict).
// B tiles fetched via cp.async into double-buffered smem; A 4-reg staging.
// grid: (7, ceil(COUT/64), NB)
// If stats != nullptr, fuses per-channel sum/sumsq (bias must be nullptr).
// Phantom columns (p0+p >= P) stay zero (cp.async zfill) -> clean stats.
// ---------------------------------------------------------------------------
template<int TCN>
__global__ __launch_bounds__(256, 2) void sgemm3(
    const float* __restrict__ X, const float* __restrict__ W,
    const float* __restrict__ bias, float* __restrict__ Y,
    int CIN, int COUT, float* __restrict__ stats)
{
    const int P  = PP;
    const int n  = blockIdx.z;
    const int m0 = blockIdx.y * 64;
    const int p0 = blockIdx.x * 256;
    const float* Xn = X + (size_t)n * (TCN ? 64 : CIN) * P;
    float*       Yn = Y + (size_t)n * COUT * P;

    __shared__ __align__(16) float As[2][16][64];
    __shared__ __align__(16) float Bs[2][16][260];

    float acc[8][8];   // [row][j]; j 0..3 -> col tx*4+j, j 4..7 -> col 128+tx*4+(j-4)
    #pragma unroll
    for (int i = 0; i < 8; i++)
        #pragma unroll
        for (int j = 0; j < 8; j++) acc[i][j] = 0.f;

    const int tx = threadIdx.x & 31;   // column group, full warp
    const int ty = threadIdx.x >> 5;   // row group (8 rows), = warp id

    const int nk = CIN / 16;
    float pa[4];

    // ---- issue B tile for k-tile `kt` into buffer `buf` via cp.async ----
    auto issueB = [&](int kt, int buf) {
        const int k0 = kt * 16;
        if (!TCN) {
            #pragma unroll
            for (int i = 0; i < 4; i++) {
                int f = threadIdx.x + i * 256;      // 0..1023 float4 slots
                int k = f >> 6, p = (f & 63) * 4;
                bool ok = (p0 + p) < P;
                const float* src = ok ? &Xn[(size_t)(k0 + k) * P + p0 + p] : Xn;
                cp16(smem_u32(&Bs[buf][k][p]), src, ok ? 16 : 0);
            }
        } else {
            #pragma unroll
            for (int i = 0; i < 16; i++) {
                int idx = threadIdx.x + i * 256;    // 0..4095
                int k = idx >> 8, p = idx & 255;
                int kk = k0 + k;
                int c = kk / 7, dt = kk % 7;
                int src = p0 + p + (dt - 3) * 25;
                bool ok = (p0 + p) < P && src >= 0 && src < P;
                const float* sp = ok ? &Xn[(size_t)c * P + src] : Xn;
                cp4(smem_u32(&Bs[buf][k][p]), sp, ok ? 4 : 0);
            }
        }
        cp_commit();
    };

    // ---- prologue: tile 0 ----
    #pragma unroll
    for (int i = 0; i < 4; i++) {
        int idx = threadIdx.x + i * 256;   // 0..1023
        int m = idx >> 4, k = idx & 15;
        float w = 0.f;
        if (m0 + m < COUT) w = W[(size_t)(m0 + m) * CIN + k];
        As[0][k][m] = w;
    }
    issueB(0, 0);

    for (int it = 0; it < nk; it++) {
        const int cur = it & 1;
        const int nxt = 1 - cur;
        const bool more = (it + 1 < nk);

        if (more) {
            issueB(it + 1, nxt);
            const int k0n = (it + 1) * 16;
            #pragma unroll
            for (int i = 0; i < 4; i++) {
                int idx = threadIdx.x + i * 256;
                int m = idx >> 4, k = idx & 15;
                float w = 0.f;
                if (m0 + m < COUT) w = W[(size_t)(m0 + m) * CIN + k0n + k];
                pa[i] = w;
            }
        }

        if (more) cp_wait<1>(); else cp_wait<0>();
        __syncthreads();

        // ---- compute current tile ----
        #pragma unroll
        for (int k = 0; k < 16; k++) {
            float a[8], b[8];
            *(float4*)a       = *(const float4*)&As[cur][k][ty * 8];
            *(float4*)(a + 4) = *(const float4*)&As[cur][k][ty * 8 + 4];
            *(float4*)b       = *(const float4*)&Bs[cur][k][tx * 4];         // 16B-stride lanes
            *(float4*)(b + 4) = *(const float4*)&Bs[cur][k][128 + tx * 4];   // 16B-stride lanes
            #pragma unroll
            for (int i = 0; i < 8; i++)
                #pragma unroll
                for (int j = 0; j < 8; j++) acc[i][j] += a[i] * b[j];
        }

        if (more) {
            #pragma unroll
            for (int i = 0; i < 4; i++) {
                int idx = threadIdx.x + i * 256;
                int m = idx >> 4, k = idx & 15;
                As[nxt][k][m] = pa[i];
            }
        }
        __syncthreads();
    }

    // ---- epilogue (split column mapping) ----
    #pragma unroll
    for (int i = 0; i < 8; i++) {
        int m = m0 + ty * 8 + i;
        if (m < COUT) {
            float bv = bias ? bias[m] : 0.f;
            int pL = p0 + tx * 4;
            if (pL < P) {
                float4 v = make_float4(acc[i][0] + bv, acc[i][1] + bv,
                                       acc[i][2] + bv, acc[i][3] + bv);
                *(float4*)&Yn[(size_t)m * P + pL] = v;
            }
            int pR = p0 + 128 + tx * 4;
            if (pR < P) {
                float4 v = make_float4(acc[i][4] + bv, acc[i][5] + bv,
                                       acc[i][6] + bv, acc[i][7] + bv);
                *(float4*)&Yn[(size_t)m * P + pR] = v;
            }
        }
    }
    if (stats) {
        #pragma unroll
        for (int i = 0; i < 8; i++) {
            float s = 0.f, s2 = 0.f;
            #pragma unroll
            for (int j = 0; j < 8; j++) { float v = acc[i][j]; s += v; s2 += v * v; }
            #pragma unroll
            for (int o = 16; o > 0; o >>= 1) {
                s  += __shfl_down_sync(0xffffffffu, s,  o);
                s2 += __shfl_down_sync(0xffffffffu, s2, o);
            }
            if (tx == 0) {
                int m = m0 + ty * 8 + i;
                if (m < COUT) {
                    atomicAdd(&stats[m], s);
                    atomicAdd(&stats[64 + m], s2);
                }
            }
        }
    }
}

// ---------------------------------------------------------------------------
// Small GEMM for qk_t (P=64 columns only).
// ---------------------------------------------------------------------------
__global__ __launch_bounds__(256) void sgemm_small(
    const float* __restrict__ X, const float* __restrict__ W,
    const float* __restrict__ bias, float* __restrict__ Y,
    int CIN, int COUT, int P)
{
    const int n  = blockIdx.z;
    const int m0 = blockIdx.y * 64;
    const float* Xn = X + (size_t)n * CIN * P;
    float*       Yn = Y + (size_t)n * COUT * P;

    __shared__ float As[16][68];
    __shared__ float Bs[16][68];
    float acc[4][4];
    #pragma unroll
    for (int i = 0; i < 4; i++)
        #pragma unroll
        for (int j = 0; j < 4; j++) acc[i][j] = 0.f;

    const int tx = threadIdx.x & 15;
    const int ty = threadIdx.x >> 4;

    for (int k0 = 0; k0 < CIN; k0 += 16) {
        for (int i = threadIdx.x; i < 64 * 16; i += 256) {
            int m = i >> 4, k = i & 15;
            float w = 0.f;
            if (m0 + m < COUT) w = W[(size_t)(m0 + m) * CIN + k0 + k];
            As[k][m] = w;
        }
        for (int i = threadIdx.x; i < 16 * 64; i += 256) {
            int k = i >> 6, p = i & 63;
            Bs[k][p] = (p < P) ? Xn[(size_t)(k0 + k) * P + p] : 0.f;
        }
        __syncthreads();
        #pragma unroll
        for (int k = 0; k < 16; k++) {
            float a[4], b[4];
            #pragma unroll
            for (int i = 0; i < 4; i++) a[i] = As[k][ty * 4 + i];
            #pragma unroll
            for (int j = 0; j < 4; j++) b[j] = Bs[k][tx * 4 + j];
            #pragma unroll
            for (int i = 0; i < 4; i++)
                #pragma unroll
                for (int j = 0; j < 4; j++) acc[i][j] += a[i] * b[j];
        }
        __syncthreads();
    }
    #pragma unroll
    for (int i = 0; i < 4; i++) {
        int m = m0 + ty * 4 + i;
        if (m < COUT) {
            float bv = bias ? bias[m] : 0.f;
            #pragma unroll
            for (int j = 0; j < 4; j++) {
                int p = tx * 4 + j;
                if (p < P) Yn[(size_t)m * P + p] = acc[i][j] + bv;
            }
        }
    }
}

// ---------------------------------------------------------------------------
// Fused spatial attention + apply: one block per (n,t).
// ---------------------------------------------------------------------------
__global__ __launch_bounds__(256) void spatial_fused(
    const float* __restrict__ x, const float* __restrict__ qk,
    const float* __restrict__ att0, const float* __restrict__ alphas,
    float* __restrict__ y)
{
    int b = blockIdx.x;
    int t = b % TT; int n = b / TT;
    __shared__ float qs[3][16][25];
    __shared__ float ks[3][16][25];
    __shared__ float xs[25][68];       // [u][c]
    __shared__ float as[3][25][26];    // [s][u][v]

    const float* base = qk + (size_t)n * 96 * PP + t * VV;
    for (int i = threadIdx.x; i < 48 * 25; i += 256) {
        int c = i / 25, u = i % 25;
        qs[c >> 4][c & 15][u] = base[(size_t)c * PP + u];
        ks[c >> 4][c & 15][u] = base[(size_t)(48 + c) * PP + u];
    }
    const float* xb = x + (size_t)n * CC * PP + t * VV;
    for (int i = threadIdx.x; i < 64 * 25; i += 256) {
        int c = i / 25, u = i % 25;
        xs[u][c] = xb[(size_t)c * PP + u];
    }
    __syncthreads();

    for (int i = threadIdx.x; i < 3 * 625; i += 256) {
        int s = i / 625, r = i % 625;
        int u = r / 25, v = r % 25;
        float d = 0.f;
        #pragma unroll
        for (int c = 0; c < 16; c++) d += qs[s][c][u] * ks[s][c][v];
        as[s][u][v] = att0[(size_t)s * 625 + r] + tanhf(d * (1.f / 16.f)) * alphas[s];
    }
    __syncthreads();

    if (threadIdx.x >= 240) return;
    int s  = threadIdx.x / 80;
    int r  = threadIdx.x % 80;
    int cg = r / 5;
    int vg = r % 5;
    float acc[4][5];
    #pragma unroll
    for (int i = 0; i < 4; i++)
        #pragma unroll
        for (int j = 0; j < 5; j++) acc[i][j] = 0.f;
    #pragma unroll
    for (int u = 0; u < 25; u++) {
        float a[4], bb[5];
        #pragma unroll
        for (int i = 0; i < 4; i++) a[i] = xs[u][cg * 4 + i];
        #pragma unroll
        for (int j = 0; j < 5; j++) bb[j] = as[s][u][vg * 5 + j];
        #pragma unroll
        for (int i = 0; i < 4; i++)
            #pragma unroll
            for (int j = 0; j < 5; j++) acc[i][j] += a[i] * bb[j];
    }
    float* yb = y + (size_t)n * 192 * PP + t * VV;
    #pragma unroll
    for (int i = 0; i < 4; i++) {
        float* yp = yb + (size_t)(s * 64 + cg * 4 + i) * PP + vg * 5;
        #pragma unroll
        for (int j = 0; j < 5; j++) yp[j] = acc[i][j];
    }
}

__global__ void zero_stats_kernel(float* s)
{
    int i = blockIdx.x * blockDim.x + threadIdx.x;
    if (i < 5 * 128) s[i] = 0.f;
}

// out = leaky( res + gamma_c*(conv-mu_c)*rsqrt(var_c+eps) + beta_c ), float4
__global__ __launch_bounds__(256) void bn_apply(
    const float4* __restrict__ conv, const float4* __restrict__ res,
    const float* __restrict__ gamma, const float* __restrict__ beta,
    const float* __restrict__ stats, float4* __restrict__ out)
{
    size_t i = (size_t)blockIdx.x * blockDim.x + threadIdx.x;
    const size_t TOT4 = (size_t)NB * CC * PP / 4;
    if (i >= TOT4) return;
    int c = (int)((i / (PP / 4)) & 63);
    float mu  = stats[c] * (1.f / (float)NTV);
    float var = stats[64 + c] * (1.f / (float)NTV) - mu * mu;
    float g = gamma[c] * rsqrtf(var + 1e-5f);
    float sh = beta[c] - mu * g;
    float4 cv = conv[i], rv = res[i], o;
    float v;
    v = rv.x + cv.x * g + sh; o.x = v > 0.f ? v : 0.1f * v;
    v = rv.y + cv.y * g + sh; o.y = v > 0.f ? v : 0.1f * v;
    v = rv.z + cv.z * g + sh; o.z = v > 0.f ? v : 0.1f * v;
    v = rv.w + cv.w * g + sh; o.w = v > 0.f ? v : 0.1f * v;
    out[i] = o;
}

// ---------------------------------------------------------------------------
// Temporal path
// ---------------------------------------------------------------------------
__global__ void mean_v_kernel(const float* __restrict__ X, float* __restrict__ xb)
{
    int i = blockIdx.x * blockDim.x + threadIdx.x;  // over N*C*T
    if (i >= NB * CC * TT) return;
    const float* p = X + (size_t)i * VV;
    float s = 0.f;
    #pragma unroll
    for (int v = 0; v < VV; v++) s += p[v];
    xb[i] = s * (1.f / (float)VV);
}

__global__ __launch_bounds__(256) void temporal_att(
    const float* __restrict__ qkt, const float* __restrict__ alphaf,
    const float* __restrict__ alphab, float* __restrict__ attt)
{
    int b = blockIdx.x;
    int slot = b & 3; int n = b >> 2;
    int dir = slot >> 1, s = slot & 1;
    int qg = (dir == 0) ? s : 2 + s;
    int kg = (dir == 0) ? 4 + s : 6 + s;
    __shared__ float qs[16][64], ks2[16][64];
    const float* base = qkt + (size_t)n * 128 * TT;
    for (int i = threadIdx.x; i < 16 * 64; i += 256) {
        int c = i >> 6, t = i & 63;
        qs [c][t] = base[(size_t)(qg * 16 + c) * TT + t];
        ks2[c][t] = base[(size_t)(kg * 16 + c) * TT + t];
    }
    __syncthreads();
    float alpha = (dir == 0) ? alphaf[s] : alphab[s];
    float* outp = attt + ((size_t)n * 4 + slot) * TT * TT;
    for (int i = threadIdx.x; i < TT * TT; i += 256) {
        int t = i >> 6, q = i & 63;
        bool keep = (dir == 0) ? (t >= q) : (q >= t);
        float d = 0.f;
        #pragma unroll
        for (int c = 0; c < 16; c++) d += qs[c][t] * ks2[c][q];
        outp[i] = keep ? tanhf(d * (1.f / 16.f)) * alpha : 0.f;
    }
}

// z[n, chbase+c, q, v] = sum_t tin[n,c,t,v] * att[t,q]
__global__ __launch_bounds__(256) void temporal_apply(
    const float* __restrict__ tin, const float* __restrict__ attt,
    float* __restrict__ z)
{
    int b = blockIdx.x;
    int slot = b & 3; int n = b >> 2;
    int dir = slot >> 1, s = slot & 1;
    int chbase = dir * 128 + s * 64;
    __shared__ float as[64][65];
    const float* ap = attt + ((size_t)n * 4 + slot) * TT * TT;
    for (int i = threadIdx.x; i < TT * TT; i += 256) as[i >> 6][i & 63] = ap[i];
    __syncthreads();
    const float* tb = tin + (size_t)n * CC * PP;
    float*       zb = z   + (size_t)n * 256 * PP;
    for (int r = threadIdx.x; r < CC * VV; r += 256) {
        int c = r / 25, v = r % 25;
        float acc[64];
        #pragma unroll
        for (int q = 0; q < 64; q++) acc[q] = 0.f;
        const float* tp = tb + (size_t)c * PP + v;
        for (int t = 0; t < 64; t++) {
            float a = tp[t * 25];
            #pragma unroll
            for (int q = 0; q < 64; q++) acc[q] += a * as[t][q];
        }
        float* zp = zb + (size_t)(chbase + c) * PP + v;
        #pragma unroll
        for (int q = 0; q < 64; q++) zp[q * 25] = acc[q];
    }
}

// ---------------------------------------------------------------------------
// Launcher
// ---------------------------------------------------------------------------
static float* sym(const void* symbol)
{
    void* p = nullptr;
    cudaGetSymbolAddress(&p, symbol);
    return (float*)p;
}

extern "C" void kernel_launch(void* const* d_in, const int* in_sizes, int n_in,
                              void* d_out, int out_size)
{
    const float* x       = (const float*)d_in[0];
    const float* att0s   = (const float*)d_in[1];
    const float* alphas  = (const float*)d_in[2];
    const float* W_qk_s  = (const float*)d_in[3];
    const float* b_qk_s  = (const float*)d_in[4];
    const float* W_outs  = (const float*)d_in[5];
    const float* g_outs  = (const float*)d_in[7];
    const float* be_outs = (const float*)d_in[8];
    const float* W_ffs   = (const float*)d_in[9];
    const float* g_ffs   = (const float*)d_in[11];
    const float* be_ffs  = (const float*)d_in[12];
    const float* W_qk_t  = (const float*)d_in[13];
    const float* b_qk_t  = (const float*)d_in[14];
    const float* al_f    = (const float*)d_in[15];
    const float* al_b    = (const float*)d_in[16];
    const float* W_outt  = (const float*)d_in[17];
    const float* g_outt  = (const float*)d_in[19];
    const float* be_outt = (const float*)d_in[20];
    const float* W_fft   = (const float*)d_in[21];
    const float* g_fft   = (const float*)d_in[23];
    const float* be_fft  = (const float*)d_in[24];
    const float* W_tcn   = (const float*)d_in[25];
    const float* g_tcn   = (const float*)d_in[27];
    const float* be_tcn  = (const float*)d_in[28];
    float* out = (float*)d_out;

    float* p_qk   = sym(g_qk);
    float* p_y    = sym(g_y);
    float* p_conv = sym(g_conv);
    float* p_sout = sym(g_sout);
    float* p_b1   = sym(g_b1);
    float* p_b2   = sym(g_b2);
    float* p_xbar = sym(g_xbar);
    float* p_qkt  = sym(g_qkt);
    float* p_attt = sym(g_attt);
    float* p_z    = sym(g_z);
    float* p_st   = sym(g_stats);

    const size_t TOT = (size_t)NB * CC * PP;
    const int EW_BLOCKS4 = (int)((TOT / 4 + 255) / 256);
    const dim3 G7(7, 1, NB);

    zero_stats_kernel<<<3, 256>>>(p_st);

    // --- spatial attention (fused att + apply) ---
    sgemm3<0><<<dim3(7, 2, NB), 256>>>(x, W_qk_s, b_qk_s, p_qk, 64, 96, nullptr);
    spatial_fused<<<NB * TT, 256>>>(x, p_qk, att0s, alphas, p_y);

    // y = BN(conv(y, W_outs)); y = leaky(x + y)   [bias cancels in BN]
    sgemm3<0><<<G7, 256>>>(p_y, W_outs, nullptr, p_conv, 192, 64, p_st + 0);
    bn_apply<<<EW_BLOCKS4, 256>>>((const float4*)p_conv, (const float4*)x,
                                  g_outs, be_outs, p_st + 0, (float4*)p_b1);

    // y = BN(conv(y, W_ffs)); s_out = leaky(x + y)
    sgemm3<0><<<G7, 256>>>(p_b1, W_ffs, nullptr, p_conv, 64, 64, p_st + 128);
    bn_apply<<<EW_BLOCKS4, 256>>>((const float4*)p_conv, (const float4*)x,
                                  g_ffs, be_ffs, p_st + 128, (float4*)p_sout);

    // --- temporal attention ---
    mean_v_kernel<<<(NB * CC * TT + 255) / 256, 256>>>(p_sout, p_xbar);
    sgemm_small<<<dim3(1, 2, NB), 256>>>(p_xbar, W_qk_t, b_qk_t, p_qkt, 64, 128, TT);
    temporal_att<<<NB * 4, 256>>>(p_qkt, al_f, al_b, p_attt);
    temporal_apply<<<NB * 4, 256>>>(p_sout, p_attt, p_z);

    // z = BN(conv(z, W_outt)); z = leaky(t_in + z)
    sgemm3<0><<<G7, 256>>>(p_z, W_outt, nullptr, p_conv, 256, 64, p_st + 256);
    bn_apply<<<EW_BLOCKS4, 256>>>((const float4*)p_conv, (const float4*)p_sout,
                                  g_outt, be_outt, p_st + 256, (float4*)p_b1);

    // z = BN(conv(z, W_fft)); z = leaky(t_in + z)
    sgemm3<0><<<G7, 256>>>(p_b1, W_fft, nullptr, p_conv, 64, 64, p_st + 384);
    bn_apply<<<EW_BLOCKS4, 256>>>((const float4*)p_conv, (const float4*)p_sout,
                                  g_fft, be_fft, p_st + 384, (float4*)p_b2);

    // --- TCN as K=448 GEMM (k = c*7+dt, shifted B rows) ---
    sgemm3<1><<<G7, 256>>>(p_b2, W_tcn, nullptr, p_conv, 448, 64, p_st + 512);
    bn_apply<<<EW_BLOCKS4, 256>>>((const float4*)p_conv, (const float4*)p_b2,
                                  g_tcn, be_tcn, p_st + 512, (float4*)out);
}

// round 11
// speedup vs baseline: 2.0090x; 1.0825x over previous
#include <cuda_runtime.h>
#include <cuda_bf16.h>
#include <math.h>
#include <cstdint>

// ---------------------------------------------------------------------------
// Problem constants
// ---------------------------------------------------------------------------
#define NB   128          // batch N
#define CC   64           // channels C = O
#define TT   64           // T
#define VV   25           // V
#define PP   (TT*VV)      // 1600 positions per (n, channel)
#define SS   3            // spatial heads
#define NTV  (NB*TT*VV)   // 204800 samples per channel for BN

// ---------------------------------------------------------------------------
// Scratch (device globals; no allocation allowed)
// ---------------------------------------------------------------------------
__device__ float g_qk  [ (size_t)NB*96*PP ];        // spatial qk conv out
__device__ float g_y   [ (size_t)NB*192*PP ];       // spatial attended
__device__ float g_conv[ (size_t)NB*CC*PP ];        // generic conv output
__device__ float g_sout[ (size_t)NB*CC*PP ];        // s_out == t_in
__device__ float g_b1  [ (size_t)NB*CC*PP ];
__device__ float g_b2  [ (size_t)NB*CC*PP ];
__device__ float g_xbar[ (size_t)NB*CC*TT ];        // mean over V
__device__ float g_qkt [ (size_t)NB*128*TT ];
__device__ float g_attt[ (size_t)NB*4*TT*TT ];      // 4 slots: f0,f1,b0,b1
__device__ float g_z   [ (size_t)NB*256*PP ];       // temporal attended
__device__ float g_stats[5*128];                    // 5 BNs x (sum[64], sumsq[64])

// ---------------------------------------------------------------------------
// cp.async helpers
// ---------------------------------------------------------------------------
__device__ __forceinline__ unsigned int smem_u32(const void* p)
{
    return (unsigned int)__cvta_generic_to_shared(p);
}
__device__ __forceinline__ void cp16(unsigned int dst, const void* src, int sbytes)
{
    asm volatile("cp.async.cg.shared.global [%0], [%1], 16, %2;"
                 :: "r"(dst), "l"(src), "r"(sbytes));
}
__device__ __forceinline__ void cp4(unsigned int dst, const void* src, int sbytes)
{
    asm volatile("cp.async.ca.shared.global [%0], [%1], 4, %2;"
                 :: "r"(dst), "l"(src), "r"(sbytes));
}
__device__ __forceinline__ void cp_commit()
{
    asm volatile("cp.async.commit_group;");
}
template<int N>
__device__ __forceinline__ void cp_wait()
{
    asm volatile("cp.async.wait_group %0;" :: "n"(N));
}

// ---------------------------------------------------------------------------
// tf32 helpers (3xTF32 error-compensated path)
// ---------------------------------------------------------------------------
__device__ __forceinline__ void split_tf32(float x, unsigned& hi, unsigned& lo)
{
    asm("cvt.rna.tf32.f32 %0, %1;" : "=r"(hi) : "f"(x));
    float r = x - __uint_as_float(hi);
    asm("cvt.rna.tf32.f32 %0, %1;" : "=r"(lo) : "f"(r));
}
__device__ __forceinline__ void mma_tf32(float* c, const unsigned* a,
                                         unsigned b0, unsigned b1)
{
    asm volatile(
        "mma.sync.aligned.m16n8k8.row.col.f32.tf32.tf32.f32 "
        "{%0,%1,%2,%3}, {%4,%5,%6,%7}, {%8,%9}, {%0,%1,%2,%3};"
        : "+f"(c[0]), "+f"(c[1]), "+f"(c[2]), "+f"(c[3])
        : "r"(a[0]), "r"(a[1]), "r"(a[2]), "r"(a[3]), "r"(b0), "r"(b1));
}

// ---------------------------------------------------------------------------
// Tensor-core GEMM (3xTF32) for 1x1 convs and the TCN-as-GEMM.
//   Y[n][m][p] = sum_k A[m][k] * B[k][p]      (per n)
// TCN==0: A=W (COUT x CIN), B[k][p] = X[n][k][p]
// TCN==1: A=W_tcn flattened (64 x 448), k=(c*7+dt),
//         B[k][p] = X[n][c][p + (dt-3)*25] with zero fill out of range.
// Tile: BM=64, BN=128, BK=16; 256 threads = 8 warps in 2(m) x 4(n) grid of
// 32x32 warp tiles; mma.m16n8k8 tf32 with hi/lo 3-term decomposition
// (hi*hi + hi*lo + lo*hi) -> fp32-grade accuracy on the tensor pipe.
// As stored [m][k] padded to 20 (fragment loads conflict-free);
// Bs [k][132] (fragment loads conflict-free). cp.async double buffering.
// grid: (13, ceil(COUT/64), NB)
// If stats != nullptr, fuses per-channel sum/sumsq (bias must be nullptr).
// Phantom columns (p0+p >= P) stay zero (cp.async zfill) -> clean stats.
// ---------------------------------------------------------------------------
template<int TCN>
__global__ __launch_bounds__(256, 2) void sgemm_tf32(
    const float* __restrict__ X, const float* __restrict__ W,
    const float* __restrict__ bias, float* __restrict__ Y,
    int CIN, int COUT, float* __restrict__ stats)
{
    const int P  = PP;
    const int n  = blockIdx.z;
    const int m0 = blockIdx.y * 64;
    const int p0 = blockIdx.x * 128;
    const float* Xn = X + (size_t)n * (TCN ? 64 : CIN) * P;
    float*       Yn = Y + (size_t)n * COUT * P;

    __shared__ __align__(16) float As[2][64][20];
    __shared__ __align__(16) float Bs[2][16][132];

    // acc[mf][nf][c]: mma fragment accumulators (2 m16-tiles x 4 n8-tiles)
    float acc[2][4][4];
    #pragma unroll
    for (int i = 0; i < 2; i++)
        #pragma unroll
        for (int j = 0; j < 4; j++)
            #pragma unroll
            for (int c = 0; c < 4; c++) acc[i][j][c] = 0.f;

    const int lane = threadIdx.x & 31;
    const int warp = threadIdx.x >> 5;
    const int g    = lane >> 2;   // groupID (row / col-group)
    const int t4   = lane & 3;    // threadID_in_group
    const int wm   = warp >> 2;   // 0..1 (m warp tile)
    const int wn   = warp & 3;    // 0..3 (n warp tile)

    const int nk = CIN / 16;
    float pa[4];

    // ---- issue B tile for k-tile `kt` into buffer `buf` via cp.async ----
    auto issueB = [&](int kt, int buf) {
        const int k0 = kt * 16;
        if (!TCN) {
            #pragma unroll
            for (int i = 0; i < 2; i++) {
                int f = threadIdx.x + i * 256;      // 0..511 float4 slots
                int k = f >> 5, p = (f & 31) * 4;
                bool ok = (p0 + p) < P;
                const float* src = ok ? &Xn[(size_t)(k0 + k) * P + p0 + p] : Xn;
                cp16(smem_u32(&Bs[buf][k][p]), src, ok ? 16 : 0);
            }
        } else {
            #pragma unroll
            for (int i = 0; i < 8; i++) {
                int idx = threadIdx.x + i * 256;    // 0..2047
                int k = idx >> 7, p = idx & 127;
                int kk = k0 + k;
                int c = kk / 7, dt = kk % 7;
                int src = p0 + p + (dt - 3) * 25;
                bool ok = (p0 + p) < P && src >= 0 && src < P;
                const float* sp = ok ? &Xn[(size_t)c * P + src] : Xn;
                cp4(smem_u32(&Bs[buf][k][p]), sp, ok ? 4 : 0);
            }
        }
        cp_commit();
    };

    // ---- prologue: tile 0 ----
    #pragma unroll
    for (int i = 0; i < 4; i++) {
        int idx = threadIdx.x + i * 256;   // 0..1023
        int m = idx >> 4, k = idx & 15;
        float w = 0.f;
        if (m0 + m < COUT) w = W[(size_t)(m0 + m) * CIN + k];
        As[0][m][k] = w;
    }
    issueB(0, 0);

    for (int it = 0; it < nk; it++) {
        const int cur = it & 1;
        const int nxt = 1 - cur;
        const bool more = (it + 1 < nk);

        if (more) {
            issueB(it + 1, nxt);
            const int k0n = (it + 1) * 16;
            #pragma unroll
            for (int i = 0; i < 4; i++) {
                int idx = threadIdx.x + i * 256;
                int m = idx >> 4, k = idx & 15;
                float w = 0.f;
                if (m0 + m < COUT) w = W[(size_t)(m0 + m) * CIN + k0n + k];
                pa[i] = w;
            }
        }

        if (more) cp_wait<1>(); else cp_wait<0>();
        __syncthreads();

        // ---- compute current tile: 2 x k8 steps ----
        #pragma unroll
        for (int ks = 0; ks < 2; ks++) {
            const int kk = ks * 8;
            unsigned ahi[2][4], alo[2][4];
            #pragma unroll
            for (int mf = 0; mf < 2; mf++) {
                int r = wm * 32 + mf * 16 + g;
                float a0 = As[cur][r    ][kk + t4];
                float a1 = As[cur][r + 8][kk + t4];
                float a2 = As[cur][r    ][kk + t4 + 4];
                float a3 = As[cur][r + 8][kk + t4 + 4];
                split_tf32(a0, ahi[mf][0], alo[mf][0]);
                split_tf32(a1, ahi[mf][1], alo[mf][1]);
                split_tf32(a2, ahi[mf][2], alo[mf][2]);
                split_tf32(a3, ahi[mf][3], alo[mf][3]);
            }
            #pragma unroll
            for (int nf = 0; nf < 4; nf++) {
                int col = wn * 32 + nf * 8 + g;
                float b0 = Bs[cur][kk + t4    ][col];
                float b1 = Bs[cur][kk + t4 + 4][col];
                unsigned bh0, bl0, bh1, bl1;
                split_tf32(b0, bh0, bl0);
                split_tf32(b1, bh1, bl1);
                #pragma unroll
                for (int mf = 0; mf < 2; mf++) {
                    mma_tf32(acc[mf][nf], ahi[mf], bh0, bh1);
                    mma_tf32(acc[mf][nf], ahi[mf], bl0, bl1);
                    mma_tf32(acc[mf][nf], alo[mf], bh0, bh1);
                }
            }
        }

        if (more) {
            #pragma unroll
            for (int i = 0; i < 4; i++) {
                int idx = threadIdx.x + i * 256;
                int m = idx >> 4, k = idx & 15;
                As[nxt][m][k] = pa[i];
            }
        }
        __syncthreads();
    }

    // ---- epilogue: fragment rows -> global ----
    #pragma unroll
    for (int mf = 0; mf < 2; mf++) {
        #pragma unroll
        for (int half = 0; half < 2; half++) {
            int m = m0 + wm * 32 + mf * 16 + g + half * 8;
            if (m < COUT) {
                float bv = bias ? bias[m] : 0.f;
                #pragma unroll
                for (int nf = 0; nf < 4; nf++) {
                    int p = p0 + wn * 32 + nf * 8 + 2 * t4;
                    if (p < P) {
                        float2 v;
                        v.x = acc[mf][nf][half * 2 + 0] + bv;
                        v.y = acc[mf][nf][half * 2 + 1] + bv;
                        *(float2*)&Yn[(size_t)m * P + p] = v;
                    }
                }
            }
        }
    }
    if (stats) {
        #pragma unroll
        for (int mf = 0; mf < 2; mf++) {
            #pragma unroll
            for (int half = 0; half < 2; half++) {
                int m = m0 + wm * 32 + mf * 16 + g + half * 8;
                float s = 0.f, s2 = 0.f;
                #pragma unroll
                for (int nf = 0; nf < 4; nf++) {
                    float v0 = acc[mf][nf][half * 2 + 0];
                    float v1 = acc[mf][nf][half * 2 + 1];
                    s  += v0 + v1;
                    s2 += v0 * v0 + v1 * v1;
                }
                // reduce across the 4 lanes (t4) sharing this fragment row
                s  += __shfl_down_sync(0xffffffffu, s,  1, 4);
                s  += __shfl_down_sync(0xffffffffu, s,  2, 4);
                s2 += __shfl_down_sync(0xffffffffu, s2, 1, 4);
                s2 += __shfl_down_sync(0xffffffffu, s2, 2, 4);
                if (t4 == 0 && m < COUT) {
                    atomicAdd(&stats[m], s);
                    atomicAdd(&stats[64 + m], s2);
                }
            }
        }
    }
}

// ---------------------------------------------------------------------------
// Small GEMM for qk_t (P=64 columns only).
// ---------------------------------------------------------------------------
__global__ __launch_bounds__(256) void sgemm_small(
    const float* __restrict__ X, const float* __restrict__ W,
    const float* __restrict__ bias, float* __restrict__ Y,
    int CIN, int COUT, int P)
{
    const int n  = blockIdx.z;
    const int m0 = blockIdx.y * 64;
    const float* Xn = X + (size_t)n * CIN * P;
    float*       Yn = Y + (size_t)n * COUT * P;

    __shared__ float As[16][68];
    __shared__ float Bs[16][68];
    float acc[4][4];
    #pragma unroll
    for (int i = 0; i < 4; i++)
        #pragma unroll
        for (int j = 0; j < 4; j++) acc[i][j] = 0.f;

    const int tx = threadIdx.x & 15;
    const int ty = threadIdx.x >> 4;

    for (int k0 = 0; k0 < CIN; k0 += 16) {
        for (int i = threadIdx.x; i < 64 * 16; i += 256) {
            int m = i >> 4, k = i & 15;
            float w = 0.f;
            if (m0 + m < COUT) w = W[(size_t)(m0 + m) * CIN + k0 + k];
            As[k][m] = w;
        }
        for (int i = threadIdx.x; i < 16 * 64; i += 256) {
            int k = i >> 6, p = i & 63;
            Bs[k][p] = (p < P) ? Xn[(size_t)(k0 + k) * P + p] : 0.f;
        }
        __syncthreads();
        #pragma unroll
        for (int k = 0; k < 16; k++) {
            float a[4], b[4];
            #pragma unroll
            for (int i = 0; i < 4; i++) a[i] = As[k][ty * 4 + i];
            #pragma unroll
            for (int j = 0; j < 4; j++) b[j] = Bs[k][tx * 4 + j];
            #pragma unroll
            for (int i = 0; i < 4; i++)
                #pragma unroll
                for (int j = 0; j < 4; j++) acc[i][j] += a[i] * b[j];
        }
        __syncthreads();
    }
    #pragma unroll
    for (int i = 0; i < 4; i++) {
        int m = m0 + ty * 4 + i;
        if (m < COUT) {
            float bv = bias ? bias[m] : 0.f;
            #pragma unroll
            for (int j = 0; j < 4; j++) {
                int p = tx * 4 + j;
                if (p < P) Yn[(size_t)m * P + p] = acc[i][j] + bv;
            }
        }
    }
}

// ---------------------------------------------------------------------------
// Fused spatial attention + apply: one block per (n,t).
// ---------------------------------------------------------------------------
__global__ __launch_bounds__(256) void spatial_fused(
    const float* __restrict__ x, const float* __restrict__ qk,
    const float* __restrict__ att0, const float* __restrict__ alphas,
    float* __restrict__ y)
{
    int b = blockIdx.x;
    int t = b % TT; int n = b / TT;
    __shared__ float qs[3][16][25];
    __shared__ float ks[3][16][25];
    __shared__ float xs[25][68];       // [u][c]
    __shared__ float as[3][25][26];    // [s][u][v]

    const float* base = qk + (size_t)n * 96 * PP + t * VV;
    for (int i = threadIdx.x; i < 48 * 25; i += 256) {
        int c = i / 25, u = i % 25;
        qs[c >> 4][c & 15][u] = base[(size_t)c * PP + u];
        ks[c >> 4][c & 15][u] = base[(size_t)(48 + c) * PP + u];
    }
    const float* xb = x + (size_t)n * CC * PP + t * VV;
    for (int i = threadIdx.x; i < 64 * 25; i += 256) {
        int c = i / 25, u = i % 25;
        xs[u][c] = xb[(size_t)c * PP + u];
    }
    __syncthreads();

    for (int i = threadIdx.x; i < 3 * 625; i += 256) {
        int s = i / 625, r = i % 625;
        int u = r / 25, v = r % 25;
        float d = 0.f;
        #pragma unroll
        for (int c = 0; c < 16; c++) d += qs[s][c][u] * ks[s][c][v];
        as[s][u][v] = att0[(size_t)s * 625 + r] + tanhf(d * (1.f / 16.f)) * alphas[s];
    }
    __syncthreads();

    if (threadIdx.x >= 240) return;
    int s  = threadIdx.x / 80;
    int r  = threadIdx.x % 80;
    int cg = r / 5;
    int vg = r % 5;
    float acc[4][5];
    #pragma unroll
    for (int i = 0; i < 4; i++)
        #pragma unroll
        for (int j = 0; j < 5; j++) acc[i][j] = 0.f;
    #pragma unroll
    for (int u = 0; u < 25; u++) {
        float a[4], bb[5];
        #pragma unroll
        for (int i = 0; i < 4; i++) a[i] = xs[u][cg * 4 + i];
        #pragma unroll
        for (int j = 0; j < 5; j++) bb[j] = as[s][u][vg * 5 + j];
        #pragma unroll
        for (int i = 0; i < 4; i++)
            #pragma unroll
            for (int j = 0; j < 5; j++) acc[i][j] += a[i] * bb[j];
    }
    float* yb = y + (size_t)n * 192 * PP + t * VV;
    #pragma unroll
    for (int i = 0; i < 4; i++) {
        float* yp = yb + (size_t)(s * 64 + cg * 4 + i) * PP + vg * 5;
        #pragma unroll
        for (int j = 0; j < 5; j++) yp[j] = acc[i][j];
    }
}

__global__ void zero_stats_kernel(float* s)
{
    int i = blockIdx.x * blockDim.x + threadIdx.x;
    if (i < 5 * 128) s[i] = 0.f;
}

// out = leaky( res + gamma_c*(conv-mu_c)*rsqrt(var_c+eps) + beta_c ), float4
__global__ __launch_bounds__(256) void bn_apply(
    const float4* __restrict__ conv, const float4* __restrict__ res,
    const float* __restrict__ gamma, const float* __restrict__ beta,
    const float* __restrict__ stats, float4* __restrict__ out)
{
    size_t i = (size_t)blockIdx.x * blockDim.x + threadIdx.x;
    const size_t TOT4 = (size_t)NB * CC * PP / 4;
    if (i >= TOT4) return;
    int c = (int)((i / (PP / 4)) & 63);
    float mu  = stats[c] * (1.f / (float)NTV);
    float var = stats[64 + c] * (1.f / (float)NTV) - mu * mu;
    float g = gamma[c] * rsqrtf(var + 1e-5f);
    float sh = beta[c] - mu * g;
    float4 cv = conv[i], rv = res[i], o;
    float v;
    v = rv.x + cv.x * g + sh; o.x = v > 0.f ? v : 0.1f * v;
    v = rv.y + cv.y * g + sh; o.y = v > 0.f ? v : 0.1f * v;
    v = rv.z + cv.z * g + sh; o.z = v > 0.f ? v : 0.1f * v;
    v = rv.w + cv.w * g + sh; o.w = v > 0.f ? v : 0.1f * v;
    out[i] = o;
}

// ---------------------------------------------------------------------------
// Temporal path
// ---------------------------------------------------------------------------
__global__ void mean_v_kernel(const float* __restrict__ X, float* __restrict__ xb)
{
    int i = blockIdx.x * blockDim.x + threadIdx.x;  // over N*C*T
    if (i >= NB * CC * TT) return;
    const float* p = X + (size_t)i * VV;
    float s = 0.f;
    #pragma unroll
    for (int v = 0; v < VV; v++) s += p[v];
    xb[i] = s * (1.f / (float)VV);
}

__global__ __launch_bounds__(256) void temporal_att(
    const float* __restrict__ qkt, const float* __restrict__ alphaf,
    const float* __restrict__ alphab, float* __restrict__ attt)
{
    int b = blockIdx.x;
    int slot = b & 3; int n = b >> 2;
    int dir = slot >> 1, s = slot & 1;
    int qg = (dir == 0) ? s : 2 + s;
    int kg = (dir == 0) ? 4 + s : 6 + s;
    __shared__ float qs[16][64], ks2[16][64];
    const float* base = qkt + (size_t)n * 128 * TT;
    for (int i = threadIdx.x; i < 16 * 64; i += 256) {
        int c = i >> 6, t = i & 63;
        qs [c][t] = base[(size_t)(qg * 16 + c) * TT + t];
        ks2[c][t] = base[(size_t)(kg * 16 + c) * TT + t];
    }
    __syncthreads();
    float alpha = (dir == 0) ? alphaf[s] : alphab[s];
    float* outp = attt + ((size_t)n * 4 + slot) * TT * TT;
    for (int i = threadIdx.x; i < TT * TT; i += 256) {
        int t = i >> 6, q = i & 63;
        bool keep = (dir == 0) ? (t >= q) : (q >= t);
        float d = 0.f;
        #pragma unroll
        for (int c = 0; c < 16; c++) d += qs[c][t] * ks2[c][q];
        outp[i] = keep ? tanhf(d * (1.f / 16.f)) * alpha : 0.f;
    }
}

// z[n, chbase+c, q, v] = sum_t tin[n,c,t,v] * att[t,q]
__global__ __launch_bounds__(256) void temporal_apply(
    const float* __restrict__ tin, const float* __restrict__ attt,
    float* __restrict__ z)
{
    int b = blockIdx.x;
    int slot = b & 3; int n = b >> 2;
    int dir = slot >> 1, s = slot & 1;
    int chbase = dir * 128 + s * 64;
    __shared__ float as[64][65];
    const float* ap = attt + ((size_t)n * 4 + slot) * TT * TT;
    for (int i = threadIdx.x; i < TT * TT; i += 256) as[i >> 6][i & 63] = ap[i];
    __syncthreads();
    const float* tb = tin + (size_t)n * CC * PP;
    float*       zb = z   + (size_t)n * 256 * PP;
    for (int r = threadIdx.x; r < CC * VV; r += 256) {
        int c = r / 25, v = r % 25;
        float acc[64];
        #pragma unroll
        for (int q = 0; q < 64; q++) acc[q] = 0.f;
        const float* tp = tb + (size_t)c * PP + v;
        for (int t = 0; t < 64; t++) {
            float a = tp[t * 25];
            #pragma unroll
            for (int q = 0; q < 64; q++) acc[q] += a * as[t][q];
        }
        float* zp = zb + (size_t)(chbase + c) * PP + v;
        #pragma unroll
        for (int q = 0; q < 64; q++) zp[q * 25] = acc[q];
    }
}

// ---------------------------------------------------------------------------
// Launcher
// ---------------------------------------------------------------------------
static float* sym(const void* symbol)
{
    void* p = nullptr;
    cudaGetSymbolAddress(&p, symbol);
    return (float*)p;
}

extern "C" void kernel_launch(void* const* d_in, const int* in_sizes, int n_in,
                              void* d_out, int out_size)
{
    const float* x       = (const float*)d_in[0];
    const float* att0s   = (const float*)d_in[1];
    const float* alphas  = (const float*)d_in[2];
    const float* W_qk_s  = (const float*)d_in[3];
    const float* b_qk_s  = (const float*)d_in[4];
    const float* W_outs  = (const float*)d_in[5];
    const float* g_outs  = (const float*)d_in[7];
    const float* be_outs = (const float*)d_in[8];
    const float* W_ffs   = (const float*)d_in[9];
    const float* g_ffs   = (const float*)d_in[11];
    const float* be_ffs  = (const float*)d_in[12];
    const float* W_qk_t  = (const float*)d_in[13];
    const float* b_qk_t  = (const float*)d_in[14];
    const float* al_f    = (const float*)d_in[15];
    const float* al_b    = (const float*)d_in[16];
    const float* W_outt  = (const float*)d_in[17];
    const float* g_outt  = (const float*)d_in[19];
    const float* be_outt = (const float*)d_in[20];
    const float* W_fft   = (const float*)d_in[21];
    const float* g_fft   = (const float*)d_in[23];
    const float* be_fft  = (const float*)d_in[24];
    const float* W_tcn   = (const float*)d_in[25];
    const float* g_tcn   = (const float*)d_in[27];
    const float* be_tcn  = (const float*)d_in[28];
    float* out = (float*)d_out;

    float* p_qk   = sym(g_qk);
    float* p_y    = sym(g_y);
    float* p_conv = sym(g_conv);
    float* p_sout = sym(g_sout);
    float* p_b1   = sym(g_b1);
    float* p_b2   = sym(g_b2);
    float* p_xbar = sym(g_xbar);
    float* p_qkt  = sym(g_qkt);
    float* p_attt = sym(g_attt);
    float* p_z    = sym(g_z);
    float* p_st   = sym(g_stats);

    const size_t TOT = (size_t)NB * CC * PP;
    const int EW_BLOCKS4 = (int)((TOT / 4 + 255) / 256);
    const dim3 G13(13, 1, NB);

    zero_stats_kernel<<<3, 256>>>(p_st);

    // --- spatial attention (fused att + apply) ---
    sgemm_tf32<0><<<dim3(13, 2, NB), 256>>>(x, W_qk_s, b_qk_s, p_qk, 64, 96, nullptr);
    spatial_fused<<<NB * TT, 256>>>(x, p_qk, att0s, alphas, p_y);

    // y = BN(conv(y, W_outs)); y = leaky(x + y)   [bias cancels in BN]
    sgemm_tf32<0><<<G13, 256>>>(p_y, W_outs, nullptr, p_conv, 192, 64, p_st + 0);
    bn_apply<<<EW_BLOCKS4, 256>>>((const float4*)p_conv, (const float4*)x,
                                  g_outs, be_outs, p_st + 0, (float4*)p_b1);

    // y = BN(conv(y, W_ffs)); s_out = leaky(x + y)
    sgemm_tf32<0><<<G13, 256>>>(p_b1, W_ffs, nullptr, p_conv, 64, 64, p_st + 128);
    bn_apply<<<EW_BLOCKS4, 256>>>((const float4*)p_conv, (const float4*)x,
                                  g_ffs, be_ffs, p_st + 128, (float4*)p_sout);

    // --- temporal attention ---
    mean_v_kernel<<<(NB * CC * TT + 255) / 256, 256>>>(p_sout, p_xbar);
    sgemm_small<<<dim3(1, 2, NB), 256>>>(p_xbar, W_qk_t, b_qk_t, p_qkt, 64, 128, TT);
    temporal_att<<<NB * 4, 256>>>(p_qkt, al_f, al_b, p_attt);
    temporal_apply<<<NB * 4, 256>>>(p_sout, p_attt, p_z);

    // z = BN(conv(z, W_outt)); z = leaky(t_in + z)
    sgemm_tf32<0><<<G13, 256>>>(p_z, W_outt, nullptr, p_conv, 256, 64, p_st + 256);
    bn_apply<<<EW_BLOCKS4, 256>>>((const float4*)p_conv, (const float4*)p_sout,
                                  g_outt, be_outt, p_st + 256, (float4*)p_b1);

    // z = BN(conv(z, W_fft)); z = leaky(t_in + z)
    sgemm_tf32<0><<<G13, 256>>>(p_b1, W_fft, nullptr, p_conv, 64, 64, p_st + 384);
    bn_apply<<<EW_BLOCKS4, 256>>>((const float4*)p_conv, (const float4*)p_sout,
                                  g_fft, be_fft, p_st + 384, (float4*)p_b2);

    // --- TCN as K=448 GEMM (k = c*7+dt, shifted B rows) ---
    sgemm_tf32<1><<<G13, 256>>>(p_b2, W_tcn, nullptr, p_conv, 448, 64, p_st + 512);
    bn_apply<<<EW_BLOCKS4, 256>>>((const float4*)p_conv, (const float4*)p_b2,
                                  g_tcn, be_tcn, p_st + 512, (float4*)out);
}